// round 1
// baseline (speedup 1.0000x reference)
#include <cuda_runtime.h>
#include <math_constants.h>

// Problem constants
#define BATCH 4
#define NTOK  4096          // H*W
#define CDIM  256
#define DDIM  32
#define MTOT  (BATCH*NTOK)  // 16384

// Scratch (allocation-free rule: device globals)
__device__ float g_q[BATCH*NTOK*DDIM];
__device__ float g_k[BATCH*NTOK*DDIM];
__device__ float g_v[BATCH*NTOK*CDIM];
__device__ float g_att[BATCH*NTOK*CDIM];

// ---------------------------------------------------------------------------
// GEMM: C[M][32] = A[M][256] @ W[256][32] + bias   (for Q and K projections)
// grid.x = M/64, 256 threads, thread tile 4x2
// ---------------------------------------------------------------------------
__global__ __launch_bounds__(256) void gemm_n32(
    const float* __restrict__ A, const float* __restrict__ W,
    const float* __restrict__ bias, float* __restrict__ C)
{
    __shared__ float As[64][33];
    __shared__ float Bs[32][32];
    const int tid = threadIdx.x;
    const int tx = tid & 15, ty = tid >> 4;
    const int m0 = blockIdx.x * 64;

    float acc[4][2] = {};
    for (int k0 = 0; k0 < 256; k0 += 32) {
#pragma unroll
        for (int i = 0; i < 8; i++) {
            int idx = tid + i*256;
            int r = idx >> 5, kk = idx & 31;
            As[r][kk] = A[(m0 + r)*256 + k0 + kk];
        }
#pragma unroll
        for (int i = 0; i < 4; i++) {
            int idx = tid + i*256;
            int r = idx >> 5, c = idx & 31;
            Bs[r][c] = W[(k0 + r)*32 + c];
        }
        __syncthreads();
#pragma unroll
        for (int kk = 0; kk < 32; kk++) {
            float b0 = Bs[kk][tx*2], b1 = Bs[kk][tx*2+1];
#pragma unroll
            for (int i = 0; i < 4; i++) {
                float av = As[ty*4+i][kk];
                acc[i][0] += av * b0;
                acc[i][1] += av * b1;
            }
        }
        __syncthreads();
    }
#pragma unroll
    for (int i = 0; i < 4; i++) {
        int m = m0 + ty*4 + i;
        C[m*32 + tx*2]     = acc[i][0] + bias[tx*2];
        C[m*32 + tx*2 + 1] = acc[i][1] + bias[tx*2 + 1];
    }
}

// ---------------------------------------------------------------------------
// GEMM: C[M][256] = A[M][256] @ W[256][256] + bias (+ residual)
// grid (M/64, 4), 256 threads, thread tile 4x4
// ---------------------------------------------------------------------------
template <bool RESID>
__global__ __launch_bounds__(256) void gemm_n256(
    const float* __restrict__ A, const float* __restrict__ W,
    const float* __restrict__ bias, const float* __restrict__ resid,
    float* __restrict__ C)
{
    __shared__ float As[64][33];
    __shared__ float Bs[32][64];
    const int tid = threadIdx.x;
    const int tx = tid & 15, ty = tid >> 4;
    const int m0 = blockIdx.x * 64;
    const int n0 = blockIdx.y * 64;

    float acc[4][4] = {};
    for (int k0 = 0; k0 < 256; k0 += 32) {
#pragma unroll
        for (int i = 0; i < 8; i++) {
            int idx = tid + i*256;
            int r = idx >> 5, kk = idx & 31;
            As[r][kk] = A[(m0 + r)*256 + k0 + kk];
        }
#pragma unroll
        for (int i = 0; i < 8; i++) {
            int idx = tid + i*256;
            int r = idx >> 6, c = idx & 63;
            Bs[r][c] = W[(k0 + r)*256 + n0 + c];
        }
        __syncthreads();
#pragma unroll
        for (int kk = 0; kk < 32; kk++) {
            float4 bv = *(const float4*)&Bs[kk][tx*4];
#pragma unroll
            for (int i = 0; i < 4; i++) {
                float av = As[ty*4+i][kk];
                acc[i][0] += av * bv.x;
                acc[i][1] += av * bv.y;
                acc[i][2] += av * bv.z;
                acc[i][3] += av * bv.w;
            }
        }
        __syncthreads();
    }
#pragma unroll
    for (int i = 0; i < 4; i++) {
        int m = m0 + ty*4 + i;
#pragma unroll
        for (int j = 0; j < 4; j++) {
            float v = acc[i][j] + bias[n0 + tx*4 + j];
            if (RESID) v += resid[m*256 + n0 + tx*4 + j];
            C[m*256 + n0 + tx*4 + j] = v;
        }
    }
}

// ---------------------------------------------------------------------------
// Flash attention (fp32): per block 64 query rows, stream 64-row K/V tiles,
// online softmax in SMEM, 4x16 register accumulators per thread.
// grid (NTOK/64, BATCH), 256 threads.
// SMEM layout (floats): Qs[64][36] Kst[32][68] Vs[64][256] Ss[64][68]
//                       rm[64] rl[64] rs[64]
// ---------------------------------------------------------------------------
#define Q_STR 36
#define K_STR 68
#define S_STR 68
#define ATT_SMEM_FLOATS (64*Q_STR + 32*K_STR + 64*256 + 64*S_STR + 192)
#define ATT_SMEM_BYTES  (ATT_SMEM_FLOATS * 4)

__global__ __launch_bounds__(256, 2) void attn_kernel()
{
    extern __shared__ float sm[];
    float* Qs  = sm;                   // [64][36]
    float* Kst = Qs  + 64*Q_STR;       // [32][68] (k-index major, transposed)
    float* Vs  = Kst + 32*K_STR;       // [64][256]
    float* Ss  = Vs  + 64*256;         // [64][68]
    float* rm  = Ss  + 64*S_STR;       // [64] running max
    float* rl  = rm + 64;              // [64] running sum
    float* rs  = rl + 64;              // [64] rescale factor for this tile

    const int tid = threadIdx.x;
    const int tx = tid & 15, ty = tid >> 4;
    const int b  = blockIdx.y;
    const int q0 = blockIdx.x * 64;

    const float* qg = g_q   + (size_t)b * NTOK * DDIM;
    const float* kg = g_k   + (size_t)b * NTOK * DDIM;
    const float* vg = g_v   + (size_t)b * NTOK * CDIM;
    float*       og = g_att + (size_t)b * NTOK * CDIM;

    // Load Q tile, pre-scaled by 1/sqrt(D)
    const float qscale = 0.17677669529663687f;
#pragma unroll
    for (int i = 0; i < 8; i++) {
        int idx = tid + i*256;
        int r = idx >> 5, kk = idx & 31;
        Qs[r*Q_STR + kk] = qg[(q0 + r)*DDIM + kk] * qscale;
    }
    if (tid < 64) { rm[tid] = -CUDART_INF_F; rl[tid] = 0.0f; }

    // Accumulator: rows ty*4+i, cols (tx*4 + c*64 + jj)
    float acc[4][16];
#pragma unroll
    for (int i = 0; i < 4; i++)
#pragma unroll
        for (int j = 0; j < 16; j++) acc[i][j] = 0.0f;

    for (int kt = 0; kt < NTOK/64; kt++) {
        const int k0 = kt * 64;
        __syncthreads();  // protect Kst/Vs from previous PV; Qs/rm on iter 0

        // Load K tile transposed: Kst[kk][row]
#pragma unroll
        for (int i = 0; i < 8; i++) {
            int idx = tid + i*256;
            int r = idx >> 5, kk = idx & 31;
            Kst[kk*K_STR + r] = kg[(k0 + r)*DDIM + kk];
        }
        // Load V tile [64][256] via float4
        const float4* vg4 = (const float4*)(vg + (size_t)k0 * CDIM);
        float4* Vs4 = (float4*)Vs;
#pragma unroll
        for (int i = 0; i < 16; i++) {
            int idx = tid + i*256;   // 4096 float4s
            Vs4[idx] = vg4[idx];
        }
        __syncthreads();

        // S[64][64] = Qs @ Kst  (thread: 4 rows x 4 cols, K-loop 32)
        float s[4][4] = {};
#pragma unroll
        for (int kk = 0; kk < 32; kk += 4) {
            float kv[4][4];
#pragma unroll
            for (int t = 0; t < 4; t++)
                *(float4*)kv[t] = *(const float4*)&Kst[(kk+t)*K_STR + tx*4];
#pragma unroll
            for (int i = 0; i < 4; i++) {
                float4 qv = *(const float4*)&Qs[(ty*4+i)*Q_STR + kk];
#pragma unroll
                for (int j = 0; j < 4; j++) {
                    s[i][j] += qv.x*kv[0][j] + qv.y*kv[1][j]
                             + qv.z*kv[2][j] + qv.w*kv[3][j];
                }
            }
        }
#pragma unroll
        for (int i = 0; i < 4; i++)
            *(float4*)&Ss[(ty*4+i)*S_STR + tx*4] = *(float4*)s[i];
        __syncthreads();

        // Online softmax: 4 threads per row, 16 elements each
        {
            const int r = tid >> 2, sub = tid & 3;
            float* row = Ss + r*S_STR + sub*16;
            float mx = row[0];
#pragma unroll
            for (int j = 1; j < 16; j++) mx = fmaxf(mx, row[j]);
            mx = fmaxf(mx, __shfl_xor_sync(0xffffffffu, mx, 1));
            mx = fmaxf(mx, __shfl_xor_sync(0xffffffffu, mx, 2));
            float newm = fmaxf(rm[r], mx);
            float sum = 0.0f;
#pragma unroll
            for (int j = 0; j < 16; j++) {
                float e = __expf(row[j] - newm);
                row[j] = e;
                sum += e;
            }
            sum += __shfl_xor_sync(0xffffffffu, sum, 1);
            sum += __shfl_xor_sync(0xffffffffu, sum, 2);
            if (sub == 0) {
                float sc = __expf(rm[r] - newm);
                rs[r] = sc;
                rl[r] = rl[r]*sc + sum;
                rm[r] = newm;
            }
        }
        __syncthreads();

        // Rescale accumulators, then acc += P @ V
#pragma unroll
        for (int i = 0; i < 4; i++) {
            float sc = rs[ty*4 + i];
#pragma unroll
            for (int j = 0; j < 16; j++) acc[i][j] *= sc;
        }
#pragma unroll 4
        for (int j = 0; j < 64; j++) {
            float p[4];
#pragma unroll
            for (int i = 0; i < 4; i++) p[i] = Ss[(ty*4+i)*S_STR + j];
#pragma unroll
            for (int c = 0; c < 4; c++) {
                float4 vv = *(const float4*)&Vs[j*256 + c*64 + tx*4];
#pragma unroll
                for (int i = 0; i < 4; i++) {
                    acc[i][c*4+0] += p[i]*vv.x;
                    acc[i][c*4+1] += p[i]*vv.y;
                    acc[i][c*4+2] += p[i]*vv.z;
                    acc[i][c*4+3] += p[i]*vv.w;
                }
            }
        }
    }

    // Epilogue: normalize by running sum, write attended
#pragma unroll
    for (int i = 0; i < 4; i++) {
        int r = q0 + ty*4 + i;
        float inv = 1.0f / rl[ty*4 + i];
#pragma unroll
        for (int c = 0; c < 4; c++) {
            float4 o;
            o.x = acc[i][c*4+0]*inv;
            o.y = acc[i][c*4+1]*inv;
            o.z = acc[i][c*4+2]*inv;
            o.w = acc[i][c*4+3]*inv;
            *(float4*)&og[(size_t)r*256 + c*64 + tx*4] = o;
        }
    }
}

// ---------------------------------------------------------------------------
// Launch
// ---------------------------------------------------------------------------
extern "C" void kernel_launch(void* const* d_in, const int* in_sizes, int n_in,
                              void* d_out, int out_size)
{
    const float* x  = (const float*)d_in[0];
    const float* wq = (const float*)d_in[1];
    const float* bq = (const float*)d_in[2];
    const float* wk = (const float*)d_in[3];
    const float* bk = (const float*)d_in[4];
    const float* wv = (const float*)d_in[5];
    const float* bv = (const float*)d_in[6];
    const float* wo = (const float*)d_in[7];
    const float* bo = (const float*)d_in[8];
    float* out = (float*)d_out;

    float *q, *k, *v, *att;
    cudaGetSymbolAddress((void**)&q,   g_q);
    cudaGetSymbolAddress((void**)&k,   g_k);
    cudaGetSymbolAddress((void**)&v,   g_v);
    cudaGetSymbolAddress((void**)&att, g_att);

    // Idempotent; needed for ~99KB dynamic smem
    cudaFuncSetAttribute(attn_kernel,
                         cudaFuncAttributeMaxDynamicSharedMemorySize,
                         ATT_SMEM_BYTES);

    gemm_n32<<<MTOT/64, 256>>>(x, wq, bq, q);
    gemm_n32<<<MTOT/64, 256>>>(x, wk, bk, k);
    gemm_n256<false><<<dim3(MTOT/64, 4), 256>>>(x, wv, bv, nullptr, v);

    attn_kernel<<<dim3(NTOK/64, BATCH), 256, ATT_SMEM_BYTES>>>();

    gemm_n256<true><<<dim3(MTOT/64, 4), 256>>>(att, wo, bo, x, out);
}

// round 2
// speedup vs baseline: 2.3976x; 2.3976x over previous
#include <cuda_runtime.h>
#include <math_constants.h>

// Problem constants
#define BATCH 4
#define NTOK  4096          // H*W
#define CDIM  256
#define DDIM  32
#define MTOT  (BATCH*NTOK)  // 16384

// Scratch (allocation-free rule: device globals)
__device__ float g_q[BATCH*NTOK*DDIM];
__device__ float g_k[BATCH*NTOK*DDIM];
__device__ float g_v[BATCH*NTOK*CDIM];
__device__ float g_att[BATCH*NTOK*CDIM];

__device__ __forceinline__ float to_tf32(float x) {
    float y;
    asm("cvt.rna.tf32.f32 %0, %1;" : "=f"(y) : "f"(x));
    return y;
}

__device__ __forceinline__ void mma_tf32(float4& c,
    unsigned a0, unsigned a1, unsigned a2, unsigned a3,
    unsigned b0, unsigned b1)
{
    asm volatile(
        "mma.sync.aligned.m16n8k8.row.col.f32.tf32.tf32.f32 "
        "{%0,%1,%2,%3}, {%4,%5,%6,%7}, {%8,%9}, {%0,%1,%2,%3};"
        : "+f"(c.x), "+f"(c.y), "+f"(c.z), "+f"(c.w)
        : "r"(a0), "r"(a1), "r"(a2), "r"(a3), "r"(b0), "r"(b1));
}

// ---------------------------------------------------------------------------
// GEMM: C[M][32] = A[M][256] @ W[256][32] + bias   (Q and K projections)
// ---------------------------------------------------------------------------
__global__ __launch_bounds__(256) void gemm_n32(
    const float* __restrict__ A, const float* __restrict__ W,
    const float* __restrict__ bias, float* __restrict__ C)
{
    __shared__ float As[64][33];
    __shared__ float Bs[32][32];
    const int tid = threadIdx.x;
    const int tx = tid & 15, ty = tid >> 4;
    const int m0 = blockIdx.x * 64;

    float acc[4][2] = {};
    for (int k0 = 0; k0 < 256; k0 += 32) {
#pragma unroll
        for (int i = 0; i < 8; i++) {
            int idx = tid + i*256;
            int r = idx >> 5, kk = idx & 31;
            As[r][kk] = A[(m0 + r)*256 + k0 + kk];
        }
#pragma unroll
        for (int i = 0; i < 4; i++) {
            int idx = tid + i*256;
            int r = idx >> 5, c = idx & 31;
            Bs[r][c] = W[(k0 + r)*32 + c];
        }
        __syncthreads();
#pragma unroll
        for (int kk = 0; kk < 32; kk++) {
            float b0 = Bs[kk][tx*2], b1 = Bs[kk][tx*2+1];
#pragma unroll
            for (int i = 0; i < 4; i++) {
                float av = As[ty*4+i][kk];
                acc[i][0] += av * b0;
                acc[i][1] += av * b1;
            }
        }
        __syncthreads();
    }
#pragma unroll
    for (int i = 0; i < 4; i++) {
        int m = m0 + ty*4 + i;
        C[m*32 + tx*2]     = acc[i][0] + bias[tx*2];
        C[m*32 + tx*2 + 1] = acc[i][1] + bias[tx*2 + 1];
    }
}

// ---------------------------------------------------------------------------
// GEMM: C[M][256] = A[M][256] @ W[256][256] + bias (+ residual)
// ---------------------------------------------------------------------------
template <bool RESID>
__global__ __launch_bounds__(256) void gemm_n256(
    const float* __restrict__ A, const float* __restrict__ W,
    const float* __restrict__ bias, const float* __restrict__ resid,
    float* __restrict__ C)
{
    __shared__ float As[64][33];
    __shared__ float Bs[32][64];
    const int tid = threadIdx.x;
    const int tx = tid & 15, ty = tid >> 4;
    const int m0 = blockIdx.x * 64;
    const int n0 = blockIdx.y * 64;

    float acc[4][4] = {};
    for (int k0 = 0; k0 < 256; k0 += 32) {
#pragma unroll
        for (int i = 0; i < 8; i++) {
            int idx = tid + i*256;
            int r = idx >> 5, kk = idx & 31;
            As[r][kk] = A[(m0 + r)*256 + k0 + kk];
        }
#pragma unroll
        for (int i = 0; i < 8; i++) {
            int idx = tid + i*256;
            int r = idx >> 6, c = idx & 63;
            Bs[r][c] = W[(k0 + r)*256 + n0 + c];
        }
        __syncthreads();
#pragma unroll
        for (int kk = 0; kk < 32; kk++) {
            float4 bv = *(const float4*)&Bs[kk][tx*4];
#pragma unroll
            for (int i = 0; i < 4; i++) {
                float av = As[ty*4+i][kk];
                acc[i][0] += av * bv.x;
                acc[i][1] += av * bv.y;
                acc[i][2] += av * bv.z;
                acc[i][3] += av * bv.w;
            }
        }
        __syncthreads();
    }
#pragma unroll
    for (int i = 0; i < 4; i++) {
        int m = m0 + ty*4 + i;
#pragma unroll
        for (int j = 0; j < 4; j++) {
            float v = acc[i][j] + bias[n0 + tx*4 + j];
            if (RESID) v += resid[m*256 + n0 + tx*4 + j];
            C[m*256 + n0 + tx*4 + j] = v;
        }
    }
}

// ---------------------------------------------------------------------------
// Flash attention with tf32 mma.sync tensor cores.
// BQ=128 query rows per CTA, BK=64 kv rows per iter, 512 threads (16 warps).
// Warp (wid): wm = wid>>1 (m-tile row block of 16), wn = wid&1 (n half).
//   Scores : warp computes S[wm*16..+16][wn*32..+32]  (4 n-tiles, k=32)
//   PV     : warp computes O[wm*16..+16][wn*128..+128] (16 n-tiles, k=64)
// SMEM strides chosen for conflict-free fragment LDS:
//   Qs stride 36, Ks stride 36, Ss stride 68, Vs stride 264.
// ---------------------------------------------------------------------------
#define BQ 128
#define BK 64
#define Q_STR 36
#define K_STR 36
#define S_STR 68
#define V_STR 264
#define ATT_SMEM_FLOATS (BQ*Q_STR + BK*K_STR + BK*V_STR + BQ*S_STR + 3*BQ)
#define ATT_SMEM_BYTES  (ATT_SMEM_FLOATS * 4)

__global__ __launch_bounds__(512, 1) void attn_kernel()
{
    extern __shared__ float sm[];
    float* Qs = sm;                    // [128][36]
    float* Ks = Qs + BQ*Q_STR;         // [64][36]   (row = key idx, col = dim)
    float* Vs = Ks + BK*K_STR;         // [64][264]  (row = key idx, col = channel)
    float* Ss = Vs + BK*V_STR;         // [128][68]
    float* rm = Ss + BQ*S_STR;         // [128] running max
    float* rl = rm + BQ;               // [128] running sum
    float* rs = rl + BQ;               // [128] per-iter rescale

    const int tid  = threadIdx.x;
    const int wid  = tid >> 5;
    const int lane = tid & 31;
    const int gid  = lane >> 2;        // 0..7
    const int tig  = lane & 3;         // 0..3
    const int wm   = wid >> 1;         // 0..7 -> m rows wm*16..
    const int wn   = wid & 1;          // 0..1

    const int b  = blockIdx.y;
    const int q0 = blockIdx.x * BQ;

    const float* qg = g_q   + (size_t)b * NTOK * DDIM;
    const float* kg = g_k   + (size_t)b * NTOK * DDIM;
    const float* vg = g_v   + (size_t)b * NTOK * CDIM;
    float*       og = g_att + (size_t)b * NTOK * CDIM;

    // Load Q tile (pre-scaled, tf32-rounded)
    const float qscale = 0.17677669529663687f;  // 1/sqrt(32)
#pragma unroll
    for (int i = 0; i < 8; i++) {
        int idx = tid + i*512;
        int r = idx >> 5, c = idx & 31;
        Qs[r*Q_STR + c] = to_tf32(qg[(q0 + r)*DDIM + c] * qscale);
    }
    if (tid < BQ) { rm[tid] = -CUDART_INF_F; rl[tid] = 0.0f; }

    // Output accumulators: 16 n-tiles x {c0,c1,c2,c3}
    float4 acc[16];
#pragma unroll
    for (int i = 0; i < 16; i++) acc[i] = make_float4(0.f, 0.f, 0.f, 0.f);

    const int arow0 = wm*16 + gid;     // rows for c0/c1 (and a0/a2)
    const int arow1 = arow0 + 8;       // rows for c2/c3 (and a1/a3)

    for (int kt = 0; kt < NTOK/BK; kt++) {
        const int k0g = kt * BK;
        __syncthreads();   // protect Ks/Vs/Ss from previous iteration readers

        // Load K tile [64][32] (tf32)
#pragma unroll
        for (int i = 0; i < 4; i++) {
            int idx = tid + i*512;
            int r = idx >> 5, c = idx & 31;
            Ks[r*K_STR + c] = to_tf32(kg[(k0g + r)*DDIM + c]);
        }
        // Load V tile [64][256] (tf32, vectorized)
        const float4* vg4 = (const float4*)(vg + (size_t)k0g * CDIM);
#pragma unroll
        for (int i = 0; i < 8; i++) {
            int idx = tid + i*512;          // 4096 float4s
            int r = idx >> 6, c4 = idx & 63;
            float4 v = vg4[idx];
            v.x = to_tf32(v.x); v.y = to_tf32(v.y);
            v.z = to_tf32(v.z); v.w = to_tf32(v.w);
            *(float4*)&Vs[r*V_STR + c4*4] = v;
        }
        __syncthreads();

        // ---- Scores: S[wm*16..+16][wn*32..+32] = Q @ K^T ----
        {
            float4 sacc[4];
#pragma unroll
            for (int i = 0; i < 4; i++) sacc[i] = make_float4(0.f,0.f,0.f,0.f);
            const int n0w = wn * 32;
#pragma unroll
            for (int k0 = 0; k0 < 32; k0 += 8) {
                unsigned a0 = __float_as_uint(Qs[arow0*Q_STR + k0 + tig]);
                unsigned a1 = __float_as_uint(Qs[arow1*Q_STR + k0 + tig]);
                unsigned a2 = __float_as_uint(Qs[arow0*Q_STR + k0 + tig + 4]);
                unsigned a3 = __float_as_uint(Qs[arow1*Q_STR + k0 + tig + 4]);
#pragma unroll
                for (int nt = 0; nt < 4; nt++) {
                    int krow = n0w + nt*8 + gid;   // key index (B col)
                    unsigned b0 = __float_as_uint(Ks[krow*K_STR + k0 + tig]);
                    unsigned b1 = __float_as_uint(Ks[krow*K_STR + k0 + tig + 4]);
                    mma_tf32(sacc[nt], a0, a1, a2, a3, b0, b1);
                }
            }
            // Write S frags to smem
#pragma unroll
            for (int nt = 0; nt < 4; nt++) {
                int c = n0w + nt*8 + 2*tig;
                *(float2*)&Ss[arow0*S_STR + c] = make_float2(sacc[nt].x, sacc[nt].y);
                *(float2*)&Ss[arow1*S_STR + c] = make_float2(sacc[nt].z, sacc[nt].w);
            }
        }
        __syncthreads();

        // ---- Online softmax: 4 threads per row, 16 cols each ----
        {
            const int r = tid >> 2, sub = tid & 3;
            float* row = Ss + r*S_STR + sub*16;
            float mx = row[0];
#pragma unroll
            for (int j = 1; j < 16; j++) mx = fmaxf(mx, row[j]);
            mx = fmaxf(mx, __shfl_xor_sync(0xffffffffu, mx, 1));
            mx = fmaxf(mx, __shfl_xor_sync(0xffffffffu, mx, 2));
            float newm = fmaxf(rm[r], mx);
            float sum = 0.0f;
#pragma unroll
            for (int j = 0; j < 16; j++) {
                float e = __expf(row[j] - newm);
                row[j] = to_tf32(e);
                sum += e;
            }
            sum += __shfl_xor_sync(0xffffffffu, sum, 1);
            sum += __shfl_xor_sync(0xffffffffu, sum, 2);
            if (sub == 0) {
                float sc = __expf(rm[r] - newm);
                rs[r] = sc;
                rl[r] = rl[r]*sc + sum;
                rm[r] = newm;
            }
        }
        __syncthreads();

        // ---- Rescale accumulators ----
        {
            float sc0 = rs[arow0], sc1 = rs[arow1];
#pragma unroll
            for (int i = 0; i < 16; i++) {
                acc[i].x *= sc0; acc[i].y *= sc0;
                acc[i].z *= sc1; acc[i].w *= sc1;
            }
        }

        // ---- PV: O[wm*16..+16][wn*128..+128] += P @ V ----
        {
            const int n0w = wn * 128;
#pragma unroll
            for (int k0 = 0; k0 < BK; k0 += 8) {
                unsigned a0 = __float_as_uint(Ss[arow0*S_STR + k0 + tig]);
                unsigned a1 = __float_as_uint(Ss[arow1*S_STR + k0 + tig]);
                unsigned a2 = __float_as_uint(Ss[arow0*S_STR + k0 + tig + 4]);
                unsigned a3 = __float_as_uint(Ss[arow1*S_STR + k0 + tig + 4]);
#pragma unroll
                for (int nt = 0; nt < 16; nt++) {
                    int vcol = n0w + nt*8 + gid;
                    unsigned b0 = __float_as_uint(Vs[(k0 + tig)*V_STR + vcol]);
                    unsigned b1 = __float_as_uint(Vs[(k0 + tig + 4)*V_STR + vcol]);
                    mma_tf32(acc[nt], a0, a1, a2, a3, b0, b1);
                }
            }
        }
    }

    // ---- Epilogue: normalize, write attended ----
    {
        float inv0 = 1.0f / rl[arow0];
        float inv1 = 1.0f / rl[arow1];
        const int n0w = wn * 128;
        float* o0 = og + (size_t)(q0 + arow0)*CDIM;
        float* o1 = og + (size_t)(q0 + arow1)*CDIM;
#pragma unroll
        for (int nt = 0; nt < 16; nt++) {
            int c = n0w + nt*8 + 2*tig;
            *(float2*)&o0[c] = make_float2(acc[nt].x*inv0, acc[nt].y*inv0);
            *(float2*)&o1[c] = make_float2(acc[nt].z*inv1, acc[nt].w*inv1);
        }
    }
}

// ---------------------------------------------------------------------------
// Launch
// ---------------------------------------------------------------------------
extern "C" void kernel_launch(void* const* d_in, const int* in_sizes, int n_in,
                              void* d_out, int out_size)
{
    const float* x  = (const float*)d_in[0];
    const float* wq = (const float*)d_in[1];
    const float* bq = (const float*)d_in[2];
    const float* wk = (const float*)d_in[3];
    const float* bk = (const float*)d_in[4];
    const float* wv = (const float*)d_in[5];
    const float* bv = (const float*)d_in[6];
    const float* wo = (const float*)d_in[7];
    const float* bo = (const float*)d_in[8];
    float* out = (float*)d_out;

    float *q, *k, *v, *att;
    cudaGetSymbolAddress((void**)&q,   g_q);
    cudaGetSymbolAddress((void**)&k,   g_k);
    cudaGetSymbolAddress((void**)&v,   g_v);
    cudaGetSymbolAddress((void**)&att, g_att);

    // Idempotent; needed for ~128KB dynamic smem
    cudaFuncSetAttribute(attn_kernel,
                         cudaFuncAttributeMaxDynamicSharedMemorySize,
                         ATT_SMEM_BYTES);

    gemm_n32<<<MTOT/64, 256>>>(x, wq, bq, q);
    gemm_n32<<<MTOT/64, 256>>>(x, wk, bk, k);
    gemm_n256<false><<<dim3(MTOT/64, 4), 256>>>(x, wv, bv, nullptr, v);

    attn_kernel<<<dim3(NTOK/BQ, BATCH), 512, ATT_SMEM_BYTES>>>();

    gemm_n256<true><<<dim3(MTOT/64, 4), 256>>>(att, wo, bo, x, out);
}

// round 3
// speedup vs baseline: 3.4154x; 1.4245x over previous
#include <cuda_runtime.h>
#include <cuda_bf16.h>
#include <math_constants.h>

// Problem constants
#define BATCH 4
#define NTOK  4096          // H*W
#define CDIM  256
#define DDIM  32
#define MTOT  (BATCH*NTOK)  // 16384

// Scratch (allocation-free rule: device globals)
__device__ __nv_bfloat16 g_q[MTOT*DDIM];
__device__ __nv_bfloat16 g_k[MTOT*DDIM];
__device__ __nv_bfloat16 g_v[MTOT*CDIM];
__device__ float         g_att[MTOT*CDIM];

// ---------------------------------------------------------------------------
// PTX helpers
// ---------------------------------------------------------------------------
__device__ __forceinline__ unsigned smem_u32(const void* p) {
    return (unsigned)__cvta_generic_to_shared(p);
}
__device__ __forceinline__ void ldm_x4(unsigned addr,
    unsigned &r0, unsigned &r1, unsigned &r2, unsigned &r3) {
    asm volatile("ldmatrix.sync.aligned.m8n8.x4.shared.b16 {%0,%1,%2,%3}, [%4];"
        : "=r"(r0), "=r"(r1), "=r"(r2), "=r"(r3) : "r"(addr));
}
__device__ __forceinline__ void ldm_x4_trans(unsigned addr,
    unsigned &r0, unsigned &r1, unsigned &r2, unsigned &r3) {
    asm volatile("ldmatrix.sync.aligned.m8n8.x4.trans.shared.b16 {%0,%1,%2,%3}, [%4];"
        : "=r"(r0), "=r"(r1), "=r"(r2), "=r"(r3) : "r"(addr));
}
__device__ __forceinline__ void ldm_x2(unsigned addr, unsigned &r0, unsigned &r1) {
    asm volatile("ldmatrix.sync.aligned.m8n8.x2.shared.b16 {%0,%1}, [%2];"
        : "=r"(r0), "=r"(r1) : "r"(addr));
}
__device__ __forceinline__ void mma_bf16(float4& c,
    unsigned a0, unsigned a1, unsigned a2, unsigned a3,
    unsigned b0, unsigned b1)
{
    asm volatile(
        "mma.sync.aligned.m16n8k16.row.col.f32.bf16.bf16.f32 "
        "{%0,%1,%2,%3}, {%4,%5,%6,%7}, {%8,%9}, {%0,%1,%2,%3};"
        : "+f"(c.x), "+f"(c.y), "+f"(c.z), "+f"(c.w)
        : "r"(a0), "r"(a1), "r"(a2), "r"(a3), "r"(b0), "r"(b1));
}

// ---------------------------------------------------------------------------
// GEMM: C[M][32] = bf16( (A[M][256] @ W[256][32] + bias) * scale )
// ---------------------------------------------------------------------------
__global__ __launch_bounds__(256) void gemm_n32(
    const float* __restrict__ A, const float* __restrict__ W,
    const float* __restrict__ bias, float scale,
    __nv_bfloat16* __restrict__ C)
{
    __shared__ float As[64][33];
    __shared__ float Bs[32][32];
    const int tid = threadIdx.x;
    const int tx = tid & 15, ty = tid >> 4;
    const int m0 = blockIdx.x * 64;

    float acc[4][2] = {};
    for (int k0 = 0; k0 < 256; k0 += 32) {
#pragma unroll
        for (int i = 0; i < 8; i++) {
            int idx = tid + i*256;
            int r = idx >> 5, kk = idx & 31;
            As[r][kk] = A[(m0 + r)*256 + k0 + kk];
        }
#pragma unroll
        for (int i = 0; i < 4; i++) {
            int idx = tid + i*256;
            int r = idx >> 5, c = idx & 31;
            Bs[r][c] = W[(k0 + r)*32 + c];
        }
        __syncthreads();
#pragma unroll
        for (int kk = 0; kk < 32; kk++) {
            float b0 = Bs[kk][tx*2], b1 = Bs[kk][tx*2+1];
#pragma unroll
            for (int i = 0; i < 4; i++) {
                float av = As[ty*4+i][kk];
                acc[i][0] += av * b0;
                acc[i][1] += av * b1;
            }
        }
        __syncthreads();
    }
#pragma unroll
    for (int i = 0; i < 4; i++) {
        int m = m0 + ty*4 + i;
        C[m*32 + tx*2]     = __float2bfloat16((acc[i][0] + bias[tx*2])     * scale);
        C[m*32 + tx*2 + 1] = __float2bfloat16((acc[i][1] + bias[tx*2 + 1]) * scale);
    }
}

// ---------------------------------------------------------------------------
// GEMM: C[M][256] = A[M][256] @ W[256][256] + bias (+ residual)
// OUT = float (out-proj) or __nv_bfloat16 (v-proj)
// ---------------------------------------------------------------------------
template <bool RESID, typename OUT>
__global__ __launch_bounds__(256) void gemm_n256(
    const float* __restrict__ A, const float* __restrict__ W,
    const float* __restrict__ bias, const float* __restrict__ resid,
    OUT* __restrict__ C)
{
    __shared__ float As[64][33];
    __shared__ float Bs[32][64];
    const int tid = threadIdx.x;
    const int tx = tid & 15, ty = tid >> 4;
    const int m0 = blockIdx.x * 64;
    const int n0 = blockIdx.y * 64;

    float acc[4][4] = {};
    for (int k0 = 0; k0 < 256; k0 += 32) {
#pragma unroll
        for (int i = 0; i < 8; i++) {
            int idx = tid + i*256;
            int r = idx >> 5, kk = idx & 31;
            As[r][kk] = A[(m0 + r)*256 + k0 + kk];
        }
#pragma unroll
        for (int i = 0; i < 8; i++) {
            int idx = tid + i*256;
            int r = idx >> 6, c = idx & 63;
            Bs[r][c] = W[(k0 + r)*256 + n0 + c];
        }
        __syncthreads();
#pragma unroll
        for (int kk = 0; kk < 32; kk++) {
            float4 bv = *(const float4*)&Bs[kk][tx*4];
#pragma unroll
            for (int i = 0; i < 4; i++) {
                float av = As[ty*4+i][kk];
                acc[i][0] += av * bv.x;
                acc[i][1] += av * bv.y;
                acc[i][2] += av * bv.z;
                acc[i][3] += av * bv.w;
            }
        }
        __syncthreads();
    }
#pragma unroll
    for (int i = 0; i < 4; i++) {
        int m = m0 + ty*4 + i;
#pragma unroll
        for (int j = 0; j < 4; j++) {
            float v = acc[i][j] + bias[n0 + tx*4 + j];
            if (RESID) v += resid[m*256 + n0 + tx*4 + j];
            C[m*256 + n0 + tx*4 + j] = (OUT)v;
        }
    }
}

// ---------------------------------------------------------------------------
// Flash attention: bf16 m16n8k16 mma + ldmatrix.
// BQ=128, BK=64, 512 threads (16 warps): wm = wid>>1 (16 m-rows), wn = wid&1.
//   Scores : S[wm*16..+16][wn*32..+32]   (4 n-tiles, 2 k-steps of 16)
//   PV     : O[wm*16..+16][wn*128..+128] (16 n-tiles, 4 k-steps of 16)
// SMEM (bf16 strides chosen so ldmatrix row addresses land in distinct banks):
//   Qs[128][40] Ks[64][40] Vs[64][264] bf16; Ss[128][68] f32; Ps[128][72] bf16
// ---------------------------------------------------------------------------
#define BQ 128
#define BK 64
#define QK_STR 40    // bf16 elems (80B rows)
#define V_STRB 264   // bf16 elems (528B rows)
#define S_STR  68    // f32
#define P_STR  72    // bf16 elems (144B rows)

#define SM_QS 0
#define SM_KS (BQ*QK_STR*2)             // 10240
#define SM_VS (SM_KS + BK*QK_STR*2)     // 15360
#define SM_SS (SM_VS + BK*V_STRB*2)     // 49152
#define SM_PS (SM_SS + BQ*S_STR*4)      // 83968
#define SM_RM (SM_PS + BQ*P_STR*2)      // 102400
#define ATT_SMEM_BYTES (SM_RM + 3*BQ*4) // 103936

__global__ __launch_bounds__(512, 1) void attn_kernel()
{
    extern __shared__ char sm[];
    __nv_bfloat16* Qs = (__nv_bfloat16*)(sm + SM_QS);
    __nv_bfloat16* Ks = (__nv_bfloat16*)(sm + SM_KS);
    __nv_bfloat16* Vs = (__nv_bfloat16*)(sm + SM_VS);
    float*         Ss = (float*)(sm + SM_SS);
    __nv_bfloat16* Ps = (__nv_bfloat16*)(sm + SM_PS);
    float* rm = (float*)(sm + SM_RM);
    float* rl = rm + BQ;
    float* rs = rl + BQ;

    const int tid  = threadIdx.x;
    const int wid  = tid >> 5;
    const int lane = tid & 31;
    const int gid  = lane >> 2;
    const int tig  = lane & 3;
    const int wm   = wid >> 1;
    const int wn   = wid & 1;

    const int b  = blockIdx.y;
    const int q0 = blockIdx.x * BQ;

    const __nv_bfloat16* qg = g_q + (size_t)b * NTOK * DDIM;
    const __nv_bfloat16* kg = g_k + (size_t)b * NTOK * DDIM;
    const __nv_bfloat16* vg = g_v + (size_t)b * NTOK * CDIM;
    float*               og = g_att + (size_t)b * NTOK * CDIM;

    // Load Q tile: 128x32 bf16 = 512 uint4
    {
        const uint4* qg4 = (const uint4*)(qg + (size_t)q0 * DDIM);
        int r = tid >> 2, c = (tid & 3) * 8;
        *(uint4*)&Qs[r*QK_STR + c] = qg4[tid];
    }
    if (tid < BQ) { rm[tid] = -CUDART_INF_F; rl[tid] = 0.0f; }

    float4 acc[16];
#pragma unroll
    for (int i = 0; i < 16; i++) acc[i] = make_float4(0.f, 0.f, 0.f, 0.f);

    // Per-lane ldmatrix address bases (bytes)
    const int arow = (lane & 7) + ((lane >> 3) & 1) * 8;  // row within 16-row A tile
    const int akof = (lane >> 4) * 8;                     // k offset 0/8
    const unsigned qa  = smem_u32(Qs) + ((wm*16 + arow)*QK_STR + akof) * 2;
    const unsigned pa  = smem_u32(Ps) + ((wm*16 + arow)*P_STR  + akof) * 2;
    const int l16 = lane & 15;
    const unsigned kb0 = smem_u32(Ks) + ((l16 & 7)*QK_STR + (l16 >> 3)*8) * 2;
    const unsigned vb0 = smem_u32(Vs) + (arow*V_STRB + akof) * 2;

    const int arow0 = wm*16 + gid;     // score/softmax row ids
    const int arow1 = arow0 + 8;

    for (int kt = 0; kt < NTOK/BK; kt++) {
        const int k0g = kt * BK;
        __syncthreads();   // protect Ks/Vs/Ps from previous iteration readers

        // Load K tile: 64x32 bf16 = 512 uint2
        {
            const uint2* kg2 = (const uint2*)(kg + (size_t)k0g * DDIM);
            int r = tid >> 3, c = (tid & 7) * 4;
            *(uint2*)&Ks[r*QK_STR + c] = kg2[tid];
        }
        // Load V tile: 64x256 bf16 = 2048 uint4
        {
            const uint4* vg4 = (const uint4*)(vg + (size_t)k0g * CDIM);
#pragma unroll
            for (int i = 0; i < 4; i++) {
                int idx = tid + i*512;
                int r = idx >> 5, c8 = idx & 31;
                *(uint4*)&Vs[r*V_STRB + c8*8] = vg4[idx];
            }
        }
        __syncthreads();

        // ---- Scores: S[wm*16..+16][wn*32..+32] = Q @ K^T ----
        {
            float4 sacc[4];
#pragma unroll
            for (int i = 0; i < 4; i++) sacc[i] = make_float4(0.f,0.f,0.f,0.f);
            const int n0w = wn * 32;
#pragma unroll
            for (int ks = 0; ks < 2; ks++) {
                unsigned a0, a1, a2, a3;
                ldm_x4(qa + ks*32, a0, a1, a2, a3);
#pragma unroll
                for (int nt = 0; nt < 4; nt++) {
                    unsigned b0, b1;
                    ldm_x2(kb0 + ((n0w + nt*8)*QK_STR)*2 + ks*32, b0, b1);
                    mma_bf16(sacc[nt], a0, a1, a2, a3, b0, b1);
                }
            }
#pragma unroll
            for (int nt = 0; nt < 4; nt++) {
                int c = n0w + nt*8 + 2*tig;
                *(float2*)&Ss[arow0*S_STR + c] = make_float2(sacc[nt].x, sacc[nt].y);
                *(float2*)&Ss[arow1*S_STR + c] = make_float2(sacc[nt].z, sacc[nt].w);
            }
        }
        __syncthreads();

        // ---- Online softmax: 4 threads/row, 16 cols each; write P in bf16 ----
        {
            const int r = tid >> 2, sub = tid & 3;
            const float* row = Ss + r*S_STR + sub*16;
            __nv_bfloat162* prow = (__nv_bfloat162*)(Ps + r*P_STR + sub*16);
            float mx = row[0];
#pragma unroll
            for (int j = 1; j < 16; j++) mx = fmaxf(mx, row[j]);
            mx = fmaxf(mx, __shfl_xor_sync(0xffffffffu, mx, 1));
            mx = fmaxf(mx, __shfl_xor_sync(0xffffffffu, mx, 2));
            float newm = fmaxf(rm[r], mx);
            float sum = 0.0f;
#pragma unroll
            for (int j = 0; j < 8; j++) {
                float e0 = __expf(row[2*j]   - newm);
                float e1 = __expf(row[2*j+1] - newm);
                sum += e0 + e1;
                prow[j] = __floats2bfloat162_rn(e0, e1);
            }
            sum += __shfl_xor_sync(0xffffffffu, sum, 1);
            sum += __shfl_xor_sync(0xffffffffu, sum, 2);
            if (sub == 0) {
                float sc = __expf(rm[r] - newm);
                rs[r] = sc;
                rl[r] = rl[r]*sc + sum;
                rm[r] = newm;
            }
        }
        __syncthreads();

        // ---- Rescale accumulators ----
        {
            float sc0 = rs[arow0], sc1 = rs[arow1];
#pragma unroll
            for (int i = 0; i < 16; i++) {
                acc[i].x *= sc0; acc[i].y *= sc0;
                acc[i].z *= sc1; acc[i].w *= sc1;
            }
        }

        // ---- PV: O[wm*16..+16][wn*128..+128] += P @ V ----
        {
            const int n0w = wn * 128;
#pragma unroll
            for (int ks = 0; ks < 4; ks++) {
                unsigned a0, a1, a2, a3;
                ldm_x4(pa + ks*32, a0, a1, a2, a3);
#pragma unroll
                for (int nt2 = 0; nt2 < 8; nt2++) {
                    unsigned b0, b1, b2, b3;
                    ldm_x4_trans(vb0 + (ks*16*V_STRB + n0w + nt2*16)*2,
                                 b0, b1, b2, b3);
                    mma_bf16(acc[nt2*2],   a0, a1, a2, a3, b0, b1);
                    mma_bf16(acc[nt2*2+1], a0, a1, a2, a3, b2, b3);
                }
            }
        }
    }

    // ---- Epilogue: normalize, write attended (fp32) ----
    {
        float inv0 = 1.0f / rl[arow0];
        float inv1 = 1.0f / rl[arow1];
        const int n0w = wn * 128;
        float* o0 = og + (size_t)(q0 + arow0)*CDIM;
        float* o1 = og + (size_t)(q0 + arow1)*CDIM;
#pragma unroll
        for (int nt = 0; nt < 16; nt++) {
            int c = n0w + nt*8 + 2*tig;
            *(float2*)&o0[c] = make_float2(acc[nt].x*inv0, acc[nt].y*inv0);
            *(float2*)&o1[c] = make_float2(acc[nt].z*inv1, acc[nt].w*inv1);
        }
    }
}

// ---------------------------------------------------------------------------
// Launch
// ---------------------------------------------------------------------------
extern "C" void kernel_launch(void* const* d_in, const int* in_sizes, int n_in,
                              void* d_out, int out_size)
{
    const float* x  = (const float*)d_in[0];
    const float* wq = (const float*)d_in[1];
    const float* bq = (const float*)d_in[2];
    const float* wk = (const float*)d_in[3];
    const float* bk = (const float*)d_in[4];
    const float* wv = (const float*)d_in[5];
    const float* bv = (const float*)d_in[6];
    const float* wo = (const float*)d_in[7];
    const float* bo = (const float*)d_in[8];
    float* out = (float*)d_out;

    __nv_bfloat16 *q, *k, *v;
    float *att;
    cudaGetSymbolAddress((void**)&q,   g_q);
    cudaGetSymbolAddress((void**)&k,   g_k);
    cudaGetSymbolAddress((void**)&v,   g_v);
    cudaGetSymbolAddress((void**)&att, g_att);

    cudaFuncSetAttribute(attn_kernel,
                         cudaFuncAttributeMaxDynamicSharedMemorySize,
                         ATT_SMEM_BYTES);

    const float qscale = 0.17677669529663687f;  // 1/sqrt(32)
    gemm_n32<<<MTOT/64, 256>>>(x, wq, bq, qscale, q);
    gemm_n32<<<MTOT/64, 256>>>(x, wk, bk, 1.0f, k);
    gemm_n256<false, __nv_bfloat16><<<dim3(MTOT/64, 4), 256>>>(x, wv, bv, nullptr, v);

    attn_kernel<<<dim3(NTOK/BQ, BATCH), 512, ATT_SMEM_BYTES>>>();

    gemm_n256<true, float><<<dim3(MTOT/64, 4), 256>>>(att, wo, bo, x, out);
}

// round 4
// speedup vs baseline: 4.9380x; 1.4458x over previous
#include <cuda_runtime.h>
#include <cuda_bf16.h>
#include <math_constants.h>

// Problem constants
#define BATCH 4
#define NTOK  4096          // H*W
#define CDIM  256
#define DDIM  32
#define MTOT  (BATCH*NTOK)  // 16384

// Scratch (allocation-free rule: device globals)
__device__ __nv_bfloat16 g_xb[MTOT*CDIM];
__device__ __nv_bfloat16 g_q[MTOT*DDIM];
__device__ __nv_bfloat16 g_k[MTOT*DDIM];
__device__ __nv_bfloat16 g_v[MTOT*CDIM];
__device__ float         g_att[MTOT*CDIM];

// ---------------------------------------------------------------------------
// PTX helpers
// ---------------------------------------------------------------------------
__device__ __forceinline__ unsigned smem_u32(const void* p) {
    return (unsigned)__cvta_generic_to_shared(p);
}
__device__ __forceinline__ void ldm_x4(unsigned addr,
    unsigned &r0, unsigned &r1, unsigned &r2, unsigned &r3) {
    asm volatile("ldmatrix.sync.aligned.m8n8.x4.shared.b16 {%0,%1,%2,%3}, [%4];"
        : "=r"(r0), "=r"(r1), "=r"(r2), "=r"(r3) : "r"(addr));
}
__device__ __forceinline__ void ldm_x4_trans(unsigned addr,
    unsigned &r0, unsigned &r1, unsigned &r2, unsigned &r3) {
    asm volatile("ldmatrix.sync.aligned.m8n8.x4.trans.shared.b16 {%0,%1,%2,%3}, [%4];"
        : "=r"(r0), "=r"(r1), "=r"(r2), "=r"(r3) : "r"(addr));
}
__device__ __forceinline__ void mma_bf16(float4& c,
    unsigned a0, unsigned a1, unsigned a2, unsigned a3,
    unsigned b0, unsigned b1)
{
    asm volatile(
        "mma.sync.aligned.m16n8k16.row.col.f32.bf16.bf16.f32 "
        "{%0,%1,%2,%3}, {%4,%5,%6,%7}, {%8,%9}, {%0,%1,%2,%3};"
        : "+f"(c.x), "+f"(c.y), "+f"(c.z), "+f"(c.w)
        : "r"(a0), "r"(a1), "r"(a2), "r"(a3), "r"(b0), "r"(b1));
}
__device__ __forceinline__ unsigned pack_bf16(float a, float b) {
    __nv_bfloat162 h = __floats2bfloat162_rn(a, b);
    return *(unsigned*)&h;
}

// ---------------------------------------------------------------------------
// x (fp32) -> bf16, one pass
// ---------------------------------------------------------------------------
__global__ __launch_bounds__(256) void xcvt_kernel(
    const float4* __restrict__ x, uint2* __restrict__ xb)
{
    int idx = blockIdx.x * 256 + threadIdx.x;   // 1,048,576 float4s
    float4 v = x[idx];
    uint2 o;
    o.x = pack_bf16(v.x, v.y);
    o.y = pack_bf16(v.z, v.w);
    xb[idx] = o;
}

// ---------------------------------------------------------------------------
// Q/K projection: C[M][32] = bf16((Xb @ W + b) * scale)
// grid (M/128, 2): y=0 -> Q (scaled), y=1 -> K. 256 threads, 8 warps m16 each.
// ---------------------------------------------------------------------------
#define PA_STR 72   // bf16 elems (144B)
#define PWQ_STR 40  // bf16 elems (80B)

__global__ __launch_bounds__(256) void proj_qk(
    const __nv_bfloat16* __restrict__ Xb,
    const float* __restrict__ wq, const float* __restrict__ bq,
    const float* __restrict__ wk, const float* __restrict__ bk,
    float qscale,
    __nv_bfloat16* __restrict__ Q, __nv_bfloat16* __restrict__ K)
{
    __shared__ __nv_bfloat16 As[128*PA_STR];
    __shared__ __nv_bfloat16 Ws[64*PWQ_STR];

    const float* W   = (blockIdx.y == 0) ? wq : wk;
    const float* bias= (blockIdx.y == 0) ? bq : bk;
    __nv_bfloat16* C = (blockIdx.y == 0) ? Q  : K;
    const float scale= (blockIdx.y == 0) ? qscale : 1.0f;

    const int tid = threadIdx.x;
    const int wid = tid >> 5, lane = tid & 31;
    const int arow = lane & 15, akof = (lane >> 4) * 8;
    const int gid = lane >> 2, tig = lane & 3;
    const int m0 = blockIdx.x * 128;

    float4 acc[4];
#pragma unroll
    for (int i = 0; i < 4; i++) acc[i] = make_float4(0.f,0.f,0.f,0.f);

    const unsigned aa = smem_u32(As) + ((wid*16 + arow)*PA_STR + akof)*2;
    const unsigned wb = smem_u32(Ws) + (arow*PWQ_STR + akof)*2;

    for (int k0 = 0; k0 < 256; k0 += 64) {
        __syncthreads();
        // A: 128x64 bf16 = 1024 uint4
#pragma unroll
        for (int i = 0; i < 4; i++) {
            int idx = tid + i*256;
            int r = idx >> 3, c8 = idx & 7;
            *(uint4*)&As[r*PA_STR + c8*8] =
                *(const uint4*)&Xb[(size_t)(m0 + r)*256 + k0 + c8*8];
        }
        // W: 64x32 fp32 -> bf16 (512 float4)
#pragma unroll
        for (int i = 0; i < 2; i++) {
            int idx = tid + i*256;
            int r = idx >> 3, c4 = idx & 7;
            float4 w = *(const float4*)&W[(k0 + r)*32 + c4*4];
            uint2 p; p.x = pack_bf16(w.x, w.y); p.y = pack_bf16(w.z, w.w);
            *(uint2*)&Ws[r*PWQ_STR + c4*4] = p;
        }
        __syncthreads();
#pragma unroll
        for (int ks = 0; ks < 4; ks++) {
            unsigned a0,a1,a2,a3;
            ldm_x4(aa + ks*32, a0,a1,a2,a3);
#pragma unroll
            for (int nt2 = 0; nt2 < 2; nt2++) {
                unsigned b0,b1,b2,b3;
                ldm_x4_trans(wb + (ks*16*PWQ_STR + nt2*16)*2, b0,b1,b2,b3);
                mma_bf16(acc[nt2*2],   a0,a1,a2,a3, b0,b1);
                mma_bf16(acc[nt2*2+1], a0,a1,a2,a3, b2,b3);
            }
        }
    }
    // epilogue
    const int r0 = m0 + wid*16 + gid;
#pragma unroll
    for (int j = 0; j < 4; j++) {
        int col = j*8 + 2*tig;
        float b0 = bias[col], b1 = bias[col+1];
        *(__nv_bfloat162*)&C[(size_t)r0*32 + col] =
            __floats2bfloat162_rn((acc[j].x + b0)*scale, (acc[j].y + b1)*scale);
        *(__nv_bfloat162*)&C[(size_t)(r0+8)*32 + col] =
            __floats2bfloat162_rn((acc[j].z + b0)*scale, (acc[j].w + b1)*scale);
    }
}

// ---------------------------------------------------------------------------
// N=256 projection: C[M][256] = A @ W + b (+resid). IN=bf16|float, OUT same.
// CTA 128x256, 8 warps in 4x2 grid (warp 32x128), k-tiled by 64.
// ---------------------------------------------------------------------------
#define PW_STR 264  // bf16 elems (528B)
#define PROJ_SMEM (128*PA_STR*2 + 64*PW_STR*2)

template<typename IN, bool RESID, typename OUT>
__global__ __launch_bounds__(256) void proj_n256(
    const IN* __restrict__ A, const float* __restrict__ W,
    const float* __restrict__ bias, const float* __restrict__ resid,
    OUT* __restrict__ C)
{
    extern __shared__ char psm[];
    __nv_bfloat16* As = (__nv_bfloat16*)psm;
    __nv_bfloat16* Ws = (__nv_bfloat16*)(psm + 128*PA_STR*2);

    const int tid = threadIdx.x;
    const int wid = tid >> 5, lane = tid & 31;
    const int wm = wid & 3, wn = wid >> 2;
    const int arow = lane & 15, akof = (lane >> 4) * 8;
    const int gid = lane >> 2, tig = lane & 3;
    const int m0 = blockIdx.x * 128;

    float4 acc[2][16];
#pragma unroll
    for (int i = 0; i < 2; i++)
#pragma unroll
        for (int j = 0; j < 16; j++) acc[i][j] = make_float4(0.f,0.f,0.f,0.f);

    const unsigned aa0 = smem_u32(As) + ((wm*32 + arow)*PA_STR + akof)*2;
    const unsigned aa1 = aa0 + 16*PA_STR*2;
    const unsigned wb  = smem_u32(Ws) + (arow*PW_STR + akof)*2;

    for (int k0 = 0; k0 < 256; k0 += 64) {
        __syncthreads();
        // A: 128x64 -> bf16
        if constexpr (sizeof(IN) == 2) {
#pragma unroll
            for (int i = 0; i < 4; i++) {
                int idx = tid + i*256;
                int r = idx >> 3, c8 = idx & 7;
                *(uint4*)&As[r*PA_STR + c8*8] =
                    *(const uint4*)&A[(size_t)(m0 + r)*256 + k0 + c8*8];
            }
        } else {
#pragma unroll
            for (int i = 0; i < 8; i++) {
                int idx = tid + i*256;          // 2048 float4
                int r = idx >> 4, c4 = idx & 15;
                float4 v = *(const float4*)&A[(size_t)(m0 + r)*256 + k0 + c4*4];
                uint2 p; p.x = pack_bf16(v.x, v.y); p.y = pack_bf16(v.z, v.w);
                *(uint2*)&As[r*PA_STR + c4*4] = p;
            }
        }
        // W: 64x256 fp32 -> bf16 (4096 float4)
#pragma unroll
        for (int i = 0; i < 16; i++) {
            int idx = tid + i*256;
            int r = idx >> 6, c4 = idx & 63;
            float4 w = *(const float4*)&W[(size_t)(k0 + r)*256 + c4*4];
            uint2 p; p.x = pack_bf16(w.x, w.y); p.y = pack_bf16(w.z, w.w);
            *(uint2*)&Ws[r*PW_STR + c4*4] = p;
        }
        __syncthreads();
#pragma unroll
        for (int ks = 0; ks < 4; ks++) {
            unsigned a00,a01,a02,a03, a10,a11,a12,a13;
            ldm_x4(aa0 + ks*32, a00,a01,a02,a03);
            ldm_x4(aa1 + ks*32, a10,a11,a12,a13);
#pragma unroll
            for (int nt = 0; nt < 8; nt++) {
                unsigned b0,b1,b2,b3;
                ldm_x4_trans(wb + (ks*16*PW_STR + wn*128 + nt*16)*2, b0,b1,b2,b3);
                mma_bf16(acc[0][nt*2],   a00,a01,a02,a03, b0,b1);
                mma_bf16(acc[0][nt*2+1], a00,a01,a02,a03, b2,b3);
                mma_bf16(acc[1][nt*2],   a10,a11,a12,a13, b0,b1);
                mma_bf16(acc[1][nt*2+1], a10,a11,a12,a13, b2,b3);
            }
        }
    }
    // epilogue
#pragma unroll
    for (int ms = 0; ms < 2; ms++) {
        int ra = m0 + wm*32 + ms*16 + gid;
        int rb = ra + 8;
#pragma unroll
        for (int j = 0; j < 16; j++) {
            int col = wn*128 + j*8 + 2*tig;
            float b0 = bias[col], b1 = bias[col+1];
            float x0 = acc[ms][j].x + b0, y0 = acc[ms][j].y + b1;
            float x1 = acc[ms][j].z + b0, y1 = acc[ms][j].w + b1;
            if (RESID) {
                float2 ra2 = *(const float2*)&resid[(size_t)ra*256 + col];
                float2 rb2 = *(const float2*)&resid[(size_t)rb*256 + col];
                x0 += ra2.x; y0 += ra2.y; x1 += rb2.x; y1 += rb2.y;
            }
            if constexpr (sizeof(OUT) == 2) {
                *(__nv_bfloat162*)&C[(size_t)ra*256 + col] = __floats2bfloat162_rn(x0, y0);
                *(__nv_bfloat162*)&C[(size_t)rb*256 + col] = __floats2bfloat162_rn(x1, y1);
            } else {
                *(float2*)&C[(size_t)ra*256 + col] = make_float2(x0, y0);
                *(float2*)&C[(size_t)rb*256 + col] = make_float2(x1, y1);
            }
        }
    }
}

// ---------------------------------------------------------------------------
// Flash attention: bf16 m16n8k16 + ldmatrix, 4x4 warp grid (32x64 PV tiles)
// BQ=128, BK=64, 512 threads (16 warps): wm = wid&3 (32 m-rows), wn = wid>>2.
// ---------------------------------------------------------------------------
#define BQ 128
#define BK 64
#define QK_STR 40    // bf16 elems (80B rows)
#define V_STRB 264   // bf16 elems (528B rows)
#define S_STR  68    // f32
#define P_STR  72    // bf16 elems (144B rows)

#define SM_QS 0
#define SM_KS (BQ*QK_STR*2)             // 10240
#define SM_VS (SM_KS + BK*QK_STR*2)     // 15360
#define SM_SS (SM_VS + BK*V_STRB*2)     // 49152
#define SM_PS (SM_SS + BQ*S_STR*4)      // 83968
#define SM_RM (SM_PS + BQ*P_STR*2)      // 102400
#define ATT_SMEM_BYTES (SM_RM + 3*BQ*4) // 103936

__global__ __launch_bounds__(512, 1) void attn_kernel()
{
    extern __shared__ char sm[];
    __nv_bfloat16* Qs = (__nv_bfloat16*)(sm + SM_QS);
    __nv_bfloat16* Ks = (__nv_bfloat16*)(sm + SM_KS);
    __nv_bfloat16* Vs = (__nv_bfloat16*)(sm + SM_VS);
    float*         Ss = (float*)(sm + SM_SS);
    __nv_bfloat16* Ps = (__nv_bfloat16*)(sm + SM_PS);
    float* rm = (float*)(sm + SM_RM);
    float* rl = rm + BQ;
    float* rs = rl + BQ;

    const int tid  = threadIdx.x;
    const int wid  = tid >> 5;
    const int lane = tid & 31;
    const int gid  = lane >> 2;
    const int tig  = lane & 3;
    const int wm   = wid & 3;      // m-block: rows wm*32..+32
    const int wn   = wid >> 2;     // n-block: scores cols wn*16, PV cols wn*64
    const int arow = lane & 15;
    const int akof = (lane >> 4) * 8;

    const int b  = blockIdx.y;
    const int q0 = blockIdx.x * BQ;

    const __nv_bfloat16* qg = g_q + (size_t)b * NTOK * DDIM;
    const __nv_bfloat16* kg = g_k + (size_t)b * NTOK * DDIM;
    const __nv_bfloat16* vg = g_v + (size_t)b * NTOK * CDIM;
    float*               og = g_att + (size_t)b * NTOK * CDIM;

    // Load Q tile: 128x32 bf16 = 512 uint4
    {
        const uint4* qg4 = (const uint4*)(qg + (size_t)q0 * DDIM);
        int r = tid >> 2, c = (tid & 3) * 8;
        *(uint4*)&Qs[r*QK_STR + c] = qg4[tid];
    }
    if (tid < BQ) { rm[tid] = -CUDART_INF_F; rl[tid] = 0.0f; }

    float4 acc[2][8];
#pragma unroll
    for (int i = 0; i < 2; i++)
#pragma unroll
        for (int j = 0; j < 8; j++) acc[i][j] = make_float4(0.f,0.f,0.f,0.f);

    const unsigned qa0 = smem_u32(Qs) + ((wm*32 + arow)*QK_STR + akof)*2;
    const unsigned qa1 = qa0 + 16*QK_STR*2;
    const unsigned pa0 = smem_u32(Ps) + ((wm*32 + arow)*P_STR + akof)*2;
    const unsigned pa1 = pa0 + 16*P_STR*2;
    const unsigned kb  = smem_u32(Ks) + ((wn*16 + arow)*QK_STR + akof)*2;
    const unsigned vb  = smem_u32(Vs) + (arow*V_STRB + akof)*2;

    for (int kt = 0; kt < NTOK/BK; kt++) {
        const int k0g = kt * BK;
        __syncthreads();   // protect Ks/Vs/Ps from previous iteration readers

        // Load K tile: 64x32 bf16 = 512 uint2
        {
            const uint2* kg2 = (const uint2*)(kg + (size_t)k0g * DDIM);
            int r = tid >> 3, c = (tid & 7) * 4;
            *(uint2*)&Ks[r*QK_STR + c] = kg2[tid];
        }
        // Load V tile: 64x256 bf16 = 2048 uint4
        {
            const uint4* vg4 = (const uint4*)(vg + (size_t)k0g * CDIM);
#pragma unroll
            for (int i = 0; i < 4; i++) {
                int idx = tid + i*512;
                int r = idx >> 5, c8 = idx & 31;
                *(uint4*)&Vs[r*V_STRB + c8*8] = vg4[idx];
            }
        }
        __syncthreads();

        // ---- Scores: S[wm*32..+32][wn*16..+16] = Q @ K^T ----
        {
            float4 sacc[2][2];
#pragma unroll
            for (int i = 0; i < 2; i++)
#pragma unroll
                for (int j = 0; j < 2; j++) sacc[i][j] = make_float4(0.f,0.f,0.f,0.f);
#pragma unroll
            for (int ks = 0; ks < 2; ks++) {
                unsigned r0,r1,r2,r3;
                ldm_x4(kb + ks*32, r0,r1,r2,r3);
                unsigned a0,a1,a2,a3;
                ldm_x4(qa0 + ks*32, a0,a1,a2,a3);
                mma_bf16(sacc[0][0], a0,a1,a2,a3, r0, r2);
                mma_bf16(sacc[0][1], a0,a1,a2,a3, r1, r3);
                ldm_x4(qa1 + ks*32, a0,a1,a2,a3);
                mma_bf16(sacc[1][0], a0,a1,a2,a3, r0, r2);
                mma_bf16(sacc[1][1], a0,a1,a2,a3, r1, r3);
            }
#pragma unroll
            for (int ms = 0; ms < 2; ms++) {
#pragma unroll
                for (int nt = 0; nt < 2; nt++) {
                    int r0r = wm*32 + ms*16 + gid;
                    int c = wn*16 + nt*8 + 2*tig;
                    *(float2*)&Ss[r0r*S_STR + c] =
                        make_float2(sacc[ms][nt].x, sacc[ms][nt].y);
                    *(float2*)&Ss[(r0r+8)*S_STR + c] =
                        make_float2(sacc[ms][nt].z, sacc[ms][nt].w);
                }
            }
        }
        __syncthreads();

        // ---- Online softmax: 4 threads/row, 16 cols each; write P in bf16 ----
        {
            const int r = tid >> 2, sub = tid & 3;
            const float* row = Ss + r*S_STR + sub*16;
            __nv_bfloat162* prow = (__nv_bfloat162*)(Ps + r*P_STR + sub*16);
            float mx = row[0];
#pragma unroll
            for (int j = 1; j < 16; j++) mx = fmaxf(mx, row[j]);
            mx = fmaxf(mx, __shfl_xor_sync(0xffffffffu, mx, 1));
            mx = fmaxf(mx, __shfl_xor_sync(0xffffffffu, mx, 2));
            float newm = fmaxf(rm[r], mx);
            float sum = 0.0f;
#pragma unroll
            for (int j = 0; j < 8; j++) {
                float e0 = __expf(row[2*j]   - newm);
                float e1 = __expf(row[2*j+1] - newm);
                sum += e0 + e1;
                prow[j] = __floats2bfloat162_rn(e0, e1);
            }
            sum += __shfl_xor_sync(0xffffffffu, sum, 1);
            sum += __shfl_xor_sync(0xffffffffu, sum, 2);
            if (sub == 0) {
                float sc = __expf(rm[r] - newm);
                rs[r] = sc;
                rl[r] = rl[r]*sc + sum;
                rm[r] = newm;
            }
        }
        __syncthreads();

        // ---- Rescale accumulators ----
#pragma unroll
        for (int ms = 0; ms < 2; ms++) {
            float sc0 = rs[wm*32 + ms*16 + gid];
            float sc1 = rs[wm*32 + ms*16 + gid + 8];
#pragma unroll
            for (int j = 0; j < 8; j++) {
                acc[ms][j].x *= sc0; acc[ms][j].y *= sc0;
                acc[ms][j].z *= sc1; acc[ms][j].w *= sc1;
            }
        }

        // ---- PV: O[wm*32..+32][wn*64..+64] += P @ V ----
#pragma unroll
        for (int ks = 0; ks < 4; ks++) {
            unsigned a00,a01,a02,a03, a10,a11,a12,a13;
            ldm_x4(pa0 + ks*32, a00,a01,a02,a03);
            ldm_x4(pa1 + ks*32, a10,a11,a12,a13);
#pragma unroll
            for (int nt = 0; nt < 4; nt++) {
                unsigned b0,b1,b2,b3;
                ldm_x4_trans(vb + (ks*16*V_STRB + wn*64 + nt*16)*2, b0,b1,b2,b3);
                mma_bf16(acc[0][nt*2],   a00,a01,a02,a03, b0,b1);
                mma_bf16(acc[0][nt*2+1], a00,a01,a02,a03, b2,b3);
                mma_bf16(acc[1][nt*2],   a10,a11,a12,a13, b0,b1);
                mma_bf16(acc[1][nt*2+1], a10,a11,a12,a13, b2,b3);
            }
        }
    }

    // ---- Epilogue: normalize, write attended (fp32) ----
#pragma unroll
    for (int ms = 0; ms < 2; ms++) {
        int r0r = q0 + wm*32 + ms*16 + gid;
        float inv0 = 1.0f / rl[wm*32 + ms*16 + gid];
        float inv1 = 1.0f / rl[wm*32 + ms*16 + gid + 8];
        float* o0 = og + (size_t)r0r*CDIM;
        float* o1 = og + (size_t)(r0r+8)*CDIM;
#pragma unroll
        for (int j = 0; j < 8; j++) {
            int c = wn*64 + j*8 + 2*tig;
            *(float2*)&o0[c] = make_float2(acc[ms][j].x*inv0, acc[ms][j].y*inv0);
            *(float2*)&o1[c] = make_float2(acc[ms][j].z*inv1, acc[ms][j].w*inv1);
        }
    }
}

// ---------------------------------------------------------------------------
// Launch
// ---------------------------------------------------------------------------
extern "C" void kernel_launch(void* const* d_in, const int* in_sizes, int n_in,
                              void* d_out, int out_size)
{
    const float* x  = (const float*)d_in[0];
    const float* wq = (const float*)d_in[1];
    const float* bq = (const float*)d_in[2];
    const float* wk = (const float*)d_in[3];
    const float* bk = (const float*)d_in[4];
    const float* wv = (const float*)d_in[5];
    const float* bv = (const float*)d_in[6];
    const float* wo = (const float*)d_in[7];
    const float* bo = (const float*)d_in[8];
    float* out = (float*)d_out;

    __nv_bfloat16 *xb, *q, *k, *v;
    float *att;
    cudaGetSymbolAddress((void**)&xb,  g_xb);
    cudaGetSymbolAddress((void**)&q,   g_q);
    cudaGetSymbolAddress((void**)&k,   g_k);
    cudaGetSymbolAddress((void**)&v,   g_v);
    cudaGetSymbolAddress((void**)&att, g_att);

    cudaFuncSetAttribute(attn_kernel,
                         cudaFuncAttributeMaxDynamicSharedMemorySize,
                         ATT_SMEM_BYTES);
    cudaFuncSetAttribute(proj_n256<__nv_bfloat16, false, __nv_bfloat16>,
                         cudaFuncAttributeMaxDynamicSharedMemorySize, PROJ_SMEM);
    cudaFuncSetAttribute(proj_n256<float, true, float>,
                         cudaFuncAttributeMaxDynamicSharedMemorySize, PROJ_SMEM);

    const float qscale = 0.17677669529663687f;  // 1/sqrt(32)

    xcvt_kernel<<<4096, 256>>>((const float4*)x, (uint2*)xb);
    proj_qk<<<dim3(MTOT/128, 2), 256>>>(xb, wq, bq, wk, bk, qscale, q, k);
    proj_n256<__nv_bfloat16, false, __nv_bfloat16>
        <<<MTOT/128, 256, PROJ_SMEM>>>(xb, wv, bv, nullptr, v);

    attn_kernel<<<dim3(NTOK/BQ, BATCH), 512, ATT_SMEM_BYTES>>>();

    proj_n256<float, true, float>
        <<<MTOT/128, 256, PROJ_SMEM>>>(att, wo, bo, x, out);
}

// round 5
// speedup vs baseline: 6.0270x; 1.2205x over previous
#include <cuda_runtime.h>
#include <cuda_bf16.h>
#include <math_constants.h>

// Problem constants
#define BATCH 4
#define NTOK  4096          // H*W
#define CDIM  256
#define DDIM  32
#define MTOT  (BATCH*NTOK)  // 16384

// Scratch (allocation-free rule: device globals)
__device__ __nv_bfloat16 g_xb[MTOT*CDIM];
__device__ __nv_bfloat16 g_q[MTOT*DDIM];
__device__ __nv_bfloat16 g_k[MTOT*DDIM];
__device__ __nv_bfloat16 g_v[MTOT*CDIM];
__device__ float         g_att[MTOT*CDIM];

// ---------------------------------------------------------------------------
// PTX helpers
// ---------------------------------------------------------------------------
__device__ __forceinline__ unsigned smem_u32(const void* p) {
    return (unsigned)__cvta_generic_to_shared(p);
}
__device__ __forceinline__ void ldm_x4(unsigned addr,
    unsigned &r0, unsigned &r1, unsigned &r2, unsigned &r3) {
    asm volatile("ldmatrix.sync.aligned.m8n8.x4.shared.b16 {%0,%1,%2,%3}, [%4];"
        : "=r"(r0), "=r"(r1), "=r"(r2), "=r"(r3) : "r"(addr));
}
__device__ __forceinline__ void ldm_x4_trans(unsigned addr,
    unsigned &r0, unsigned &r1, unsigned &r2, unsigned &r3) {
    asm volatile("ldmatrix.sync.aligned.m8n8.x4.trans.shared.b16 {%0,%1,%2,%3}, [%4];"
        : "=r"(r0), "=r"(r1), "=r"(r2), "=r"(r3) : "r"(addr));
}
__device__ __forceinline__ void mma_bf16(float4& c,
    unsigned a0, unsigned a1, unsigned a2, unsigned a3,
    unsigned b0, unsigned b1)
{
    asm volatile(
        "mma.sync.aligned.m16n8k16.row.col.f32.bf16.bf16.f32 "
        "{%0,%1,%2,%3}, {%4,%5,%6,%7}, {%8,%9}, {%0,%1,%2,%3};"
        : "+f"(c.x), "+f"(c.y), "+f"(c.z), "+f"(c.w)
        : "r"(a0), "r"(a1), "r"(a2), "r"(a3), "r"(b0), "r"(b1));
}
__device__ __forceinline__ unsigned pack_bf16(float a, float b) {
    __nv_bfloat162 h = __floats2bfloat162_rn(a, b);
    return *(unsigned*)&h;
}
__device__ __forceinline__ float fast_ex2(float x) {
    float y;
    asm("ex2.approx.ftz.f32 %0, %1;" : "=f"(y) : "f"(x));
    return y;
}
__device__ __forceinline__ void cp16(unsigned dst, const void* src) {
    asm volatile("cp.async.cg.shared.global [%0], [%1], 16;"
        :: "r"(dst), "l"(src));
}
__device__ __forceinline__ void cp_commit() {
    asm volatile("cp.async.commit_group;");
}

// ---------------------------------------------------------------------------
// x (fp32) -> bf16, one pass
// ---------------------------------------------------------------------------
__global__ __launch_bounds__(256) void xcvt_kernel(
    const float4* __restrict__ x, uint2* __restrict__ xb)
{
    int idx = blockIdx.x * 256 + threadIdx.x;   // 1,048,576 float4s
    float4 v = x[idx];
    uint2 o;
    o.x = pack_bf16(v.x, v.y);
    o.y = pack_bf16(v.z, v.w);
    xb[idx] = o;
}

// ---------------------------------------------------------------------------
// Q/K projection: C[M][32] = bf16((Xb @ W + b) * scale)
// grid (M/128, 2): y=0 -> Q (scaled by 1/sqrt(d)*log2e), y=1 -> K.
// ---------------------------------------------------------------------------
#define PA_STR 72   // bf16 elems (144B)
#define PWQ_STR 40  // bf16 elems (80B)

__global__ __launch_bounds__(256) void proj_qk(
    const __nv_bfloat16* __restrict__ Xb,
    const float* __restrict__ wq, const float* __restrict__ bq,
    const float* __restrict__ wk, const float* __restrict__ bk,
    float qscale,
    __nv_bfloat16* __restrict__ Q, __nv_bfloat16* __restrict__ K)
{
    __shared__ __nv_bfloat16 As[128*PA_STR];
    __shared__ __nv_bfloat16 Ws[64*PWQ_STR];

    const float* W   = (blockIdx.y == 0) ? wq : wk;
    const float* bias= (blockIdx.y == 0) ? bq : bk;
    __nv_bfloat16* C = (blockIdx.y == 0) ? Q  : K;
    const float scale= (blockIdx.y == 0) ? qscale : 1.0f;

    const int tid = threadIdx.x;
    const int wid = tid >> 5, lane = tid & 31;
    const int arow = lane & 15, akof = (lane >> 4) * 8;
    const int gid = lane >> 2, tig = lane & 3;
    const int m0 = blockIdx.x * 128;

    float4 acc[4];
#pragma unroll
    for (int i = 0; i < 4; i++) acc[i] = make_float4(0.f,0.f,0.f,0.f);

    const unsigned aa = smem_u32(As) + ((wid*16 + arow)*PA_STR + akof)*2;
    const unsigned wb = smem_u32(Ws) + (arow*PWQ_STR + akof)*2;

    for (int k0 = 0; k0 < 256; k0 += 64) {
        __syncthreads();
        // A: 128x64 bf16 = 1024 uint4
#pragma unroll
        for (int i = 0; i < 4; i++) {
            int idx = tid + i*256;
            int r = idx >> 3, c8 = idx & 7;
            *(uint4*)&As[r*PA_STR + c8*8] =
                *(const uint4*)&Xb[(size_t)(m0 + r)*256 + k0 + c8*8];
        }
        // W: 64x32 fp32 -> bf16 (512 float4)
#pragma unroll
        for (int i = 0; i < 2; i++) {
            int idx = tid + i*256;
            int r = idx >> 3, c4 = idx & 7;
            float4 w = *(const float4*)&W[(k0 + r)*32 + c4*4];
            uint2 p; p.x = pack_bf16(w.x, w.y); p.y = pack_bf16(w.z, w.w);
            *(uint2*)&Ws[r*PWQ_STR + c4*4] = p;
        }
        __syncthreads();
#pragma unroll
        for (int ks = 0; ks < 4; ks++) {
            unsigned a0,a1,a2,a3;
            ldm_x4(aa + ks*32, a0,a1,a2,a3);
#pragma unroll
            for (int nt2 = 0; nt2 < 2; nt2++) {
                unsigned b0,b1,b2,b3;
                ldm_x4_trans(wb + (ks*16*PWQ_STR + nt2*16)*2, b0,b1,b2,b3);
                mma_bf16(acc[nt2*2],   a0,a1,a2,a3, b0,b1);
                mma_bf16(acc[nt2*2+1], a0,a1,a2,a3, b2,b3);
            }
        }
    }
    // epilogue
    const int r0 = m0 + wid*16 + gid;
#pragma unroll
    for (int j = 0; j < 4; j++) {
        int col = j*8 + 2*tig;
        float b0 = bias[col], b1 = bias[col+1];
        *(__nv_bfloat162*)&C[(size_t)r0*32 + col] =
            __floats2bfloat162_rn((acc[j].x + b0)*scale, (acc[j].y + b1)*scale);
        *(__nv_bfloat162*)&C[(size_t)(r0+8)*32 + col] =
            __floats2bfloat162_rn((acc[j].z + b0)*scale, (acc[j].w + b1)*scale);
    }
}

// ---------------------------------------------------------------------------
// N=256 projection: C[M][256] = A @ W + b (+resid). IN=bf16|float, OUT same.
// ---------------------------------------------------------------------------
#define PW_STR 264  // bf16 elems (528B)
#define PROJ_SMEM (128*PA_STR*2 + 64*PW_STR*2)

template<typename IN, bool RESID, typename OUT>
__global__ __launch_bounds__(256) void proj_n256(
    const IN* __restrict__ A, const float* __restrict__ W,
    const float* __restrict__ bias, const float* __restrict__ resid,
    OUT* __restrict__ C)
{
    extern __shared__ char psm[];
    __nv_bfloat16* As = (__nv_bfloat16*)psm;
    __nv_bfloat16* Ws = (__nv_bfloat16*)(psm + 128*PA_STR*2);

    const int tid = threadIdx.x;
    const int wid = tid >> 5, lane = tid & 31;
    const int wm = wid & 3, wn = wid >> 2;
    const int arow = lane & 15, akof = (lane >> 4) * 8;
    const int gid = lane >> 2, tig = lane & 3;
    const int m0 = blockIdx.x * 128;

    float4 acc[2][16];
#pragma unroll
    for (int i = 0; i < 2; i++)
#pragma unroll
        for (int j = 0; j < 16; j++) acc[i][j] = make_float4(0.f,0.f,0.f,0.f);

    const unsigned aa0 = smem_u32(As) + ((wm*32 + arow)*PA_STR + akof)*2;
    const unsigned aa1 = aa0 + 16*PA_STR*2;
    const unsigned wb  = smem_u32(Ws) + (arow*PW_STR + akof)*2;

    for (int k0 = 0; k0 < 256; k0 += 64) {
        __syncthreads();
        if constexpr (sizeof(IN) == 2) {
#pragma unroll
            for (int i = 0; i < 4; i++) {
                int idx = tid + i*256;
                int r = idx >> 3, c8 = idx & 7;
                *(uint4*)&As[r*PA_STR + c8*8] =
                    *(const uint4*)&A[(size_t)(m0 + r)*256 + k0 + c8*8];
            }
        } else {
#pragma unroll
            for (int i = 0; i < 8; i++) {
                int idx = tid + i*256;          // 2048 float4
                int r = idx >> 4, c4 = idx & 15;
                float4 v = *(const float4*)&A[(size_t)(m0 + r)*256 + k0 + c4*4];
                uint2 p; p.x = pack_bf16(v.x, v.y); p.y = pack_bf16(v.z, v.w);
                *(uint2*)&As[r*PA_STR + c4*4] = p;
            }
        }
        // W: 64x256 fp32 -> bf16 (4096 float4)
#pragma unroll
        for (int i = 0; i < 16; i++) {
            int idx = tid + i*256;
            int r = idx >> 6, c4 = idx & 63;
            float4 w = *(const float4*)&W[(size_t)(k0 + r)*256 + c4*4];
            uint2 p; p.x = pack_bf16(w.x, w.y); p.y = pack_bf16(w.z, w.w);
            *(uint2*)&Ws[r*PW_STR + c4*4] = p;
        }
        __syncthreads();
#pragma unroll
        for (int ks = 0; ks < 4; ks++) {
            unsigned a00,a01,a02,a03, a10,a11,a12,a13;
            ldm_x4(aa0 + ks*32, a00,a01,a02,a03);
            ldm_x4(aa1 + ks*32, a10,a11,a12,a13);
#pragma unroll
            for (int nt = 0; nt < 8; nt++) {
                unsigned b0,b1,b2,b3;
                ldm_x4_trans(wb + (ks*16*PW_STR + wn*128 + nt*16)*2, b0,b1,b2,b3);
                mma_bf16(acc[0][nt*2],   a00,a01,a02,a03, b0,b1);
                mma_bf16(acc[0][nt*2+1], a00,a01,a02,a03, b2,b3);
                mma_bf16(acc[1][nt*2],   a10,a11,a12,a13, b0,b1);
                mma_bf16(acc[1][nt*2+1], a10,a11,a12,a13, b2,b3);
            }
        }
    }
    // epilogue
#pragma unroll
    for (int ms = 0; ms < 2; ms++) {
        int ra = m0 + wm*32 + ms*16 + gid;
        int rb = ra + 8;
#pragma unroll
        for (int j = 0; j < 16; j++) {
            int col = wn*128 + j*8 + 2*tig;
            float b0 = bias[col], b1 = bias[col+1];
            float x0 = acc[ms][j].x + b0, y0 = acc[ms][j].y + b1;
            float x1 = acc[ms][j].z + b0, y1 = acc[ms][j].w + b1;
            if (RESID) {
                float2 ra2 = *(const float2*)&resid[(size_t)ra*256 + col];
                float2 rb2 = *(const float2*)&resid[(size_t)rb*256 + col];
                x0 += ra2.x; y0 += ra2.y; x1 += rb2.x; y1 += rb2.y;
            }
            if constexpr (sizeof(OUT) == 2) {
                *(__nv_bfloat162*)&C[(size_t)ra*256 + col] = __floats2bfloat162_rn(x0, y0);
                *(__nv_bfloat162*)&C[(size_t)rb*256 + col] = __floats2bfloat162_rn(x1, y1);
            } else {
                *(float2*)&C[(size_t)ra*256 + col] = make_float2(x0, y0);
                *(float2*)&C[(size_t)rb*256 + col] = make_float2(x1, y1);
            }
        }
    }
}

// ---------------------------------------------------------------------------
// Flash attention, register-resident softmax (no S/P SMEM round-trip).
// BQ=128, BK=64, 512 threads, 16 warps: wm = wid&7 (16 rows), wn = wid>>3
// (PV col half of 128). Each warp computes its full 16x64 score strip
// (QK duplicated across the 2 wn halves), softmax entirely in registers,
// score C-fragments repacked in-register as bf16 A-fragments for PV.
// K/V double-buffered via cp.async.
// ---------------------------------------------------------------------------
#define BQ 128
#define BK 64
#define NT (NTOK/BK)
#define QK_STR 40    // bf16 elems (80B rows)
#define V_STRB 264   // bf16 elems (528B rows)

#define SM_QS  0
#define SM_KS0 (BQ*QK_STR*2)             // 10240
#define SM_KS1 (SM_KS0 + BK*QK_STR*2)    // 15360
#define SM_VS0 (SM_KS1 + BK*QK_STR*2)    // 20480
#define SM_VS1 (SM_VS0 + BK*V_STRB*2)    // 54272
#define ATT_SMEM_BYTES (SM_VS1 + BK*V_STRB*2)  // 88064

__global__ __launch_bounds__(512, 1) void attn_kernel()
{
    extern __shared__ char sm[];
    const unsigned smb = smem_u32(sm);

    const int tid  = threadIdx.x;
    const int wid  = tid >> 5;
    const int lane = tid & 31;
    const int gid  = lane >> 2;
    const int tig  = lane & 3;
    const int wm   = wid & 7;      // rows wm*16 .. +16
    const int wn   = wid >> 3;     // PV cols wn*128 .. +128
    const int arow = lane & 15;
    const int akof = (lane >> 4) * 8;

    const int b  = blockIdx.y;
    const int q0 = blockIdx.x * BQ;

    const __nv_bfloat16* qg = g_q + (size_t)b * NTOK * DDIM;
    const __nv_bfloat16* kg = g_k + (size_t)b * NTOK * DDIM;
    const __nv_bfloat16* vg = g_v + (size_t)b * NTOK * CDIM;
    float*               og = g_att + (size_t)b * NTOK * CDIM;

    // Prologue: async-load Q tile + K/V tile 0 into buffer 0
    {
        // Q: 128x32 bf16 = 512 x 16B
        int r = tid >> 2, c8 = (tid & 3) * 8;
        cp16(smb + SM_QS + (r*QK_STR + c8)*2, qg + (size_t)q0*DDIM + r*DDIM + c8);
        // K tile 0: 64x32 = 256 x 16B
        if (tid < 256) {
            int kr = tid >> 2, kc = (tid & 3) * 8;
            cp16(smb + SM_KS0 + (kr*QK_STR + kc)*2, kg + kr*DDIM + kc);
        }
        // V tile 0: 64x256 = 2048 x 16B
#pragma unroll
        for (int i = 0; i < 4; i++) {
            int idx = tid + i*512;
            int vr = idx >> 5, vc = (idx & 31) * 8;
            cp16(smb + SM_VS0 + (vr*V_STRB + vc)*2, vg + vr*CDIM + vc);
        }
        cp_commit();
    }

    float4 acc[16];
#pragma unroll
    for (int j = 0; j < 16; j++) acc[j] = make_float4(0.f,0.f,0.f,0.f);
    float rm0 = -1e30f, rm1 = -1e30f, rl0 = 0.f, rl1 = 0.f;

    const unsigned qa = smb + SM_QS + ((wm*16 + arow)*QK_STR + akof)*2;

    for (int kt = 0; kt < NT; kt++) {
        const int cur = kt & 1;
        const unsigned kbase = smb + (cur ? SM_KS1 : SM_KS0);
        const unsigned vbase = smb + (cur ? SM_VS1 : SM_VS0);

        // Issue next tile's loads into the other buffer
        if (kt + 1 < NT) {
            const int nk0 = (kt + 1) * BK;
            const unsigned kn = smb + (cur ? SM_KS0 : SM_KS1);
            const unsigned vn = smb + (cur ? SM_VS0 : SM_VS1);
            if (tid < 256) {
                int kr = tid >> 2, kc = (tid & 3) * 8;
                cp16(kn + (kr*QK_STR + kc)*2, kg + (size_t)(nk0 + kr)*DDIM + kc);
            }
#pragma unroll
            for (int i = 0; i < 4; i++) {
                int idx = tid + i*512;
                int vr = idx >> 5, vc = (idx & 31) * 8;
                cp16(vn + (vr*V_STRB + vc)*2, vg + (size_t)(nk0 + vr)*CDIM + vc);
            }
            cp_commit();
            asm volatile("cp.async.wait_group 1;");
        } else {
            asm volatile("cp.async.wait_group 0;");
        }
        __syncthreads();

        // ---- Scores: S[wm*16..+16][0..64] = Q @ K^T (full strip per warp)
        float4 sacc[8];
#pragma unroll
        for (int i = 0; i < 8; i++) sacc[i] = make_float4(0.f,0.f,0.f,0.f);
        const unsigned kb = kbase + (arow*QK_STR + akof)*2;
#pragma unroll
        for (int ks = 0; ks < 2; ks++) {
            unsigned a0,a1,a2,a3;
            ldm_x4(qa + ks*32, a0,a1,a2,a3);
#pragma unroll
            for (int g = 0; g < 4; g++) {
                unsigned r0,r1,r2,r3;
                ldm_x4(kb + (g*16*QK_STR)*2 + ks*32, r0,r1,r2,r3);
                mma_bf16(sacc[g*2],   a0,a1,a2,a3, r0, r2);
                mma_bf16(sacc[g*2+1], a0,a1,a2,a3, r1, r3);
            }
        }

        // ---- Register softmax (rows gid and gid+8 of this warp's strip)
        float m0 = sacc[0].x, m1 = sacc[0].z;
#pragma unroll
        for (int t = 0; t < 8; t++) {
            m0 = fmaxf(m0, fmaxf(sacc[t].x, sacc[t].y));
            m1 = fmaxf(m1, fmaxf(sacc[t].z, sacc[t].w));
        }
        m0 = fmaxf(m0, __shfl_xor_sync(0xffffffffu, m0, 1));
        m0 = fmaxf(m0, __shfl_xor_sync(0xffffffffu, m0, 2));
        m1 = fmaxf(m1, __shfl_xor_sync(0xffffffffu, m1, 1));
        m1 = fmaxf(m1, __shfl_xor_sync(0xffffffffu, m1, 2));
        const float nm0 = fmaxf(rm0, m0), nm1 = fmaxf(rm1, m1);
        const float c0 = fast_ex2(rm0 - nm0), c1 = fast_ex2(rm1 - nm1);
        rm0 = nm0; rm1 = nm1;

        float s0 = 0.f, s1 = 0.f;
#pragma unroll
        for (int t = 0; t < 8; t++) {
            sacc[t].x = fast_ex2(sacc[t].x - nm0);
            sacc[t].y = fast_ex2(sacc[t].y - nm0);
            sacc[t].z = fast_ex2(sacc[t].z - nm1);
            sacc[t].w = fast_ex2(sacc[t].w - nm1);
            s0 += sacc[t].x + sacc[t].y;
            s1 += sacc[t].z + sacc[t].w;
        }
        s0 += __shfl_xor_sync(0xffffffffu, s0, 1);
        s0 += __shfl_xor_sync(0xffffffffu, s0, 2);
        s1 += __shfl_xor_sync(0xffffffffu, s1, 1);
        s1 += __shfl_xor_sync(0xffffffffu, s1, 2);
        rl0 = rl0*c0 + s0;
        rl1 = rl1*c1 + s1;

        // Rescale accumulators
#pragma unroll
        for (int j = 0; j < 16; j++) {
            acc[j].x *= c0; acc[j].y *= c0;
            acc[j].z *= c1; acc[j].w *= c1;
        }

        // Pack P C-fragments directly into bf16 A-fragments (k-blocks of 16)
        unsigned af[4][4];
#pragma unroll
        for (int kk = 0; kk < 4; kk++) {
            af[kk][0] = pack_bf16(sacc[2*kk].x,   sacc[2*kk].y);
            af[kk][1] = pack_bf16(sacc[2*kk].z,   sacc[2*kk].w);
            af[kk][2] = pack_bf16(sacc[2*kk+1].x, sacc[2*kk+1].y);
            af[kk][3] = pack_bf16(sacc[2*kk+1].z, sacc[2*kk+1].w);
        }

        // ---- PV: O[wm*16..+16][wn*128..+128] += P @ V
        const unsigned vb = vbase + (arow*V_STRB + akof)*2;
#pragma unroll
        for (int ks = 0; ks < 4; ks++) {
#pragma unroll
            for (int nt = 0; nt < 8; nt++) {
                unsigned b0,b1,b2,b3;
                ldm_x4_trans(vb + (ks*16*V_STRB + wn*128 + nt*16)*2, b0,b1,b2,b3);
                mma_bf16(acc[nt*2],   af[ks][0],af[ks][1],af[ks][2],af[ks][3], b0,b1);
                mma_bf16(acc[nt*2+1], af[ks][0],af[ks][1],af[ks][2],af[ks][3], b2,b3);
            }
        }
        __syncthreads();   // protect cur buffers before next iteration's issue
    }

    // ---- Epilogue: normalize, write attended (fp32) ----
    {
        const float inv0 = 1.0f / rl0;
        const float inv1 = 1.0f / rl1;
        float* o0 = og + (size_t)(q0 + wm*16 + gid)*CDIM;
        float* o1 = o0 + 8*CDIM;
#pragma unroll
        for (int j = 0; j < 16; j++) {
            int c = wn*128 + j*8 + 2*tig;
            *(float2*)&o0[c] = make_float2(acc[j].x*inv0, acc[j].y*inv0);
            *(float2*)&o1[c] = make_float2(acc[j].z*inv1, acc[j].w*inv1);
        }
    }
}

// ---------------------------------------------------------------------------
// Launch
// ---------------------------------------------------------------------------
extern "C" void kernel_launch(void* const* d_in, const int* in_sizes, int n_in,
                              void* d_out, int out_size)
{
    const float* x  = (const float*)d_in[0];
    const float* wq = (const float*)d_in[1];
    const float* bq = (const float*)d_in[2];
    const float* wk = (const float*)d_in[3];
    const float* bk = (const float*)d_in[4];
    const float* wv = (const float*)d_in[5];
    const float* bv = (const float*)d_in[6];
    const float* wo = (const float*)d_in[7];
    const float* bo = (const float*)d_in[8];
    float* out = (float*)d_out;

    __nv_bfloat16 *xb, *q, *k, *v;
    float *att;
    cudaGetSymbolAddress((void**)&xb,  g_xb);
    cudaGetSymbolAddress((void**)&q,   g_q);
    cudaGetSymbolAddress((void**)&k,   g_k);
    cudaGetSymbolAddress((void**)&v,   g_v);
    cudaGetSymbolAddress((void**)&att, g_att);

    cudaFuncSetAttribute(attn_kernel,
                         cudaFuncAttributeMaxDynamicSharedMemorySize,
                         ATT_SMEM_BYTES);
    cudaFuncSetAttribute(proj_n256<__nv_bfloat16, false, __nv_bfloat16>,
                         cudaFuncAttributeMaxDynamicSharedMemorySize, PROJ_SMEM);
    cudaFuncSetAttribute(proj_n256<float, true, float>,
                         cudaFuncAttributeMaxDynamicSharedMemorySize, PROJ_SMEM);

    // (1/sqrt(32)) * log2(e): softmax done with ex2
    const float qscale = 0.17677669529663687f * 1.4426950408889634f;

    xcvt_kernel<<<4096, 256>>>((const float4*)x, (uint2*)xb);
    proj_qk<<<dim3(MTOT/128, 2), 256>>>(xb, wq, bq, wk, bk, qscale, q, k);
    proj_n256<__nv_bfloat16, false, __nv_bfloat16>
        <<<MTOT/128, 256, PROJ_SMEM>>>(xb, wv, bv, nullptr, v);

    attn_kernel<<<dim3(NTOK/BQ, BATCH), 512, ATT_SMEM_BYTES>>>();

    proj_n256<float, true, float>
        <<<MTOT/128, 256, PROJ_SMEM>>>(att, wo, bo, x, out);
}

// round 11
// speedup vs baseline: 7.0643x; 1.1721x over previous
#include <cuda_runtime.h>
#include <cuda_bf16.h>

// Problem constants
#define BATCH 4
#define NTOK  4096
#define CDIM  256
#define DDIM  32
#define MTOT  (BATCH*NTOK)

// Scratch (allocation-free rule: device globals)
__device__ __nv_bfloat16 g_q[MTOT*DDIM];
__device__ __nv_bfloat16 g_k[MTOT*DDIM];
__device__ __nv_bfloat16 g_v[MTOT*CDIM];
__device__ __nv_bfloat16 g_att[MTOT*CDIM];

// ---------------------------------------------------------------------------
// PTX helpers
// ---------------------------------------------------------------------------
__device__ __forceinline__ unsigned smem_u32(const void* p) {
    return (unsigned)__cvta_generic_to_shared(p);
}
__device__ __forceinline__ void ldm_x4(unsigned addr,
    unsigned &r0, unsigned &r1, unsigned &r2, unsigned &r3) {
    asm volatile("ldmatrix.sync.aligned.m8n8.x4.shared.b16 {%0,%1,%2,%3}, [%4];"
        : "=r"(r0), "=r"(r1), "=r"(r2), "=r"(r3) : "r"(addr));
}
__device__ __forceinline__ void ldm_x4_trans(unsigned addr,
    unsigned &r0, unsigned &r1, unsigned &r2, unsigned &r3) {
    asm volatile("ldmatrix.sync.aligned.m8n8.x4.trans.shared.b16 {%0,%1,%2,%3}, [%4];"
        : "=r"(r0), "=r"(r1), "=r"(r2), "=r"(r3) : "r"(addr));
}
__device__ __forceinline__ void mma_bf16(float4& c,
    unsigned a0, unsigned a1, unsigned a2, unsigned a3,
    unsigned b0, unsigned b1)
{
    asm volatile(
        "mma.sync.aligned.m16n8k16.row.col.f32.bf16.bf16.f32 "
        "{%0,%1,%2,%3}, {%4,%5,%6,%7}, {%8,%9}, {%0,%1,%2,%3};"
        : "+f"(c.x), "+f"(c.y), "+f"(c.z), "+f"(c.w)
        : "r"(a0), "r"(a1), "r"(a2), "r"(a3), "r"(b0), "r"(b1));
}
__device__ __forceinline__ unsigned pack_bf16(float a, float b) {
    __nv_bfloat162 h = __floats2bfloat162_rn(a, b);
    return *(unsigned*)&h;
}
__device__ __forceinline__ float fast_ex2(float x) {
    float y;
    asm("ex2.approx.ftz.f32 %0, %1;" : "=f"(y) : "f"(x));
    return y;
}
__device__ __forceinline__ void cp16(unsigned dst, const void* src) {
    asm volatile("cp.async.cg.shared.global [%0], [%1], 16;"
        :: "r"(dst), "l"(src));
}
__device__ __forceinline__ void cp_commit() {
    asm volatile("cp.async.commit_group;");
}

// ---------------------------------------------------------------------------
// Q/K projection from fp32 x: C[M][32] = bf16((x @ W + b) * scale)
// grid (M/128, 2): y=0 -> Q (scale includes log2e/sqrt(d)), y=1 -> K.
// ---------------------------------------------------------------------------
#define PA_STR 72
#define PWQ_STR 40

__global__ __launch_bounds__(256) void proj_qk(
    const float* __restrict__ X,
    const float* __restrict__ wq, const float* __restrict__ bq,
    const float* __restrict__ wk, const float* __restrict__ bk,
    float qscale,
    __nv_bfloat16* __restrict__ Q, __nv_bfloat16* __restrict__ K)
{
    __shared__ __nv_bfloat16 As[128*PA_STR];
    __shared__ __nv_bfloat16 Ws[64*PWQ_STR];

    const float* W    = (blockIdx.y == 0) ? wq : wk;
    const float* bias = (blockIdx.y == 0) ? bq : bk;
    __nv_bfloat16* C  = (blockIdx.y == 0) ? Q  : K;
    const float scale = (blockIdx.y == 0) ? qscale : 1.0f;

    const int tid = threadIdx.x;
    const int wid = tid >> 5, lane = tid & 31;
    const int arow = lane & 15, akof = (lane >> 4) * 8;
    const int gid = lane >> 2, tig = lane & 3;
    const int m0 = blockIdx.x * 128;

    float4 acc[4];
#pragma unroll
    for (int i = 0; i < 4; i++) acc[i] = make_float4(0.f,0.f,0.f,0.f);

    const unsigned aa = smem_u32(As) + ((wid*16 + arow)*PA_STR + akof)*2;
    const unsigned wb = smem_u32(Ws) + (arow*PWQ_STR + akof)*2;

    for (int k0 = 0; k0 < 256; k0 += 64) {
        __syncthreads();
#pragma unroll
        for (int i = 0; i < 8; i++) {                // 128x64 fp32 -> bf16
            int idx = tid + i*256;
            int r = idx >> 4, c4 = idx & 15;
            float4 v = *(const float4*)&X[(size_t)(m0 + r)*256 + k0 + c4*4];
            uint2 p; p.x = pack_bf16(v.x, v.y); p.y = pack_bf16(v.z, v.w);
            *(uint2*)&As[r*PA_STR + c4*4] = p;
        }
#pragma unroll
        for (int i = 0; i < 2; i++) {                // 64x32 fp32 -> bf16
            int idx = tid + i*256;
            int r = idx >> 3, c4 = idx & 7;
            float4 w = *(const float4*)&W[(k0 + r)*32 + c4*4];
            uint2 p; p.x = pack_bf16(w.x, w.y); p.y = pack_bf16(w.z, w.w);
            *(uint2*)&Ws[r*PWQ_STR + c4*4] = p;
        }
        __syncthreads();
#pragma unroll
        for (int ks = 0; ks < 4; ks++) {
            unsigned a0,a1,a2,a3;
            ldm_x4(aa + ks*32, a0,a1,a2,a3);
#pragma unroll
            for (int nt2 = 0; nt2 < 2; nt2++) {
                unsigned b0,b1,b2,b3;
                ldm_x4_trans(wb + (ks*16*PWQ_STR + nt2*16)*2, b0,b1,b2,b3);
                mma_bf16(acc[nt2*2],   a0,a1,a2,a3, b0,b1);
                mma_bf16(acc[nt2*2+1], a0,a1,a2,a3, b2,b3);
            }
        }
    }
    const int r0 = m0 + wid*16 + gid;
#pragma unroll
    for (int j = 0; j < 4; j++) {
        int col = j*8 + 2*tig;
        float b0 = bias[col], b1 = bias[col+1];
        *(__nv_bfloat162*)&C[(size_t)r0*32 + col] =
            __floats2bfloat162_rn((acc[j].x + b0)*scale, (acc[j].y + b1)*scale);
        *(__nv_bfloat162*)&C[(size_t)(r0+8)*32 + col] =
            __floats2bfloat162_rn((acc[j].z + b0)*scale, (acc[j].w + b1)*scale);
    }
}

// ---------------------------------------------------------------------------
// N=256 projection: C[M][256] = A @ W + b (+resid). IN=bf16|float, OUT same.
// CTA 128x256, 8 warps in 4x2 grid, k-tiled by 64.
// ---------------------------------------------------------------------------
#define PW_STR 264
#define PROJ_SMEM (128*PA_STR*2 + 64*PW_STR*2)

template<typename IN, bool RESID, typename OUT>
__global__ __launch_bounds__(256) void proj_n256(
    const IN* __restrict__ A, const float* __restrict__ W,
    const float* __restrict__ bias, const float* __restrict__ resid,
    OUT* __restrict__ C)
{
    extern __shared__ char psm[];
    __nv_bfloat16* As = (__nv_bfloat16*)psm;
    __nv_bfloat16* Ws = (__nv_bfloat16*)(psm + 128*PA_STR*2);

    const int tid = threadIdx.x;
    const int wid = tid >> 5, lane = tid & 31;
    const int wm = wid & 3, wn = wid >> 2;
    const int arow = lane & 15, akof = (lane >> 4) * 8;
    const int gid = lane >> 2, tig = lane & 3;
    const int m0 = blockIdx.x * 128;

    float4 acc[2][16];
#pragma unroll
    for (int i = 0; i < 2; i++)
#pragma unroll
        for (int j = 0; j < 16; j++) acc[i][j] = make_float4(0.f,0.f,0.f,0.f);

    const unsigned aa0 = smem_u32(As) + ((wm*32 + arow)*PA_STR + akof)*2;
    const unsigned aa1 = aa0 + 16*PA_STR*2;
    const unsigned wb  = smem_u32(Ws) + (arow*PW_STR + akof)*2;

    for (int k0 = 0; k0 < 256; k0 += 64) {
        __syncthreads();
        if constexpr (sizeof(IN) == 2) {
#pragma unroll
            for (int i = 0; i < 4; i++) {
                int idx = tid + i*256;
                int r = idx >> 3, c8 = idx & 7;
                *(uint4*)&As[r*PA_STR + c8*8] =
                    *(const uint4*)&A[(size_t)(m0 + r)*256 + k0 + c8*8];
            }
        } else {
#pragma unroll
            for (int i = 0; i < 8; i++) {
                int idx = tid + i*256;
                int r = idx >> 4, c4 = idx & 15;
                float4 v = *(const float4*)&A[(size_t)(m0 + r)*256 + k0 + c4*4];
                uint2 p; p.x = pack_bf16(v.x, v.y); p.y = pack_bf16(v.z, v.w);
                *(uint2*)&As[r*PA_STR + c4*4] = p;
            }
        }
#pragma unroll
        for (int i = 0; i < 16; i++) {
            int idx = tid + i*256;
            int r = idx >> 6, c4 = idx & 63;
            float4 w = *(const float4*)&W[(size_t)(k0 + r)*256 + c4*4];
            uint2 p; p.x = pack_bf16(w.x, w.y); p.y = pack_bf16(w.z, w.w);
            *(uint2*)&Ws[r*PW_STR + c4*4] = p;
        }
        __syncthreads();
#pragma unroll
        for (int ks = 0; ks < 4; ks++) {
            unsigned a00,a01,a02,a03, a10,a11,a12,a13;
            ldm_x4(aa0 + ks*32, a00,a01,a02,a03);
            ldm_x4(aa1 + ks*32, a10,a11,a12,a13);
#pragma unroll
            for (int nt = 0; nt < 8; nt++) {
                unsigned b0,b1,b2,b3;
                ldm_x4_trans(wb + (ks*16*PW_STR + wn*128 + nt*16)*2, b0,b1,b2,b3);
                mma_bf16(acc[0][nt*2],   a00,a01,a02,a03, b0,b1);
                mma_bf16(acc[0][nt*2+1], a00,a01,a02,a03, b2,b3);
                mma_bf16(acc[1][nt*2],   a10,a11,a12,a13, b0,b1);
                mma_bf16(acc[1][nt*2+1], a10,a11,a12,a13, b2,b3);
            }
        }
    }
#pragma unroll
    for (int ms = 0; ms < 2; ms++) {
        int ra = m0 + wm*32 + ms*16 + gid;
        int rb = ra + 8;
#pragma unroll
        for (int j = 0; j < 16; j++) {
            int col = wn*128 + j*8 + 2*tig;
            float b0 = bias[col], b1 = bias[col+1];
            float x0 = acc[ms][j].x + b0, y0 = acc[ms][j].y + b1;
            float x1 = acc[ms][j].z + b0, y1 = acc[ms][j].w + b1;
            if (RESID) {
                float2 ra2 = *(const float2*)&resid[(size_t)ra*256 + col];
                float2 rb2 = *(const float2*)&resid[(size_t)rb*256 + col];
                x0 += ra2.x; y0 += ra2.y; x1 += rb2.x; y1 += rb2.y;
            }
            if constexpr (sizeof(OUT) == 2) {
                *(__nv_bfloat162*)&C[(size_t)ra*256 + col] = __floats2bfloat162_rn(x0, y0);
                *(__nv_bfloat162*)&C[(size_t)rb*256 + col] = __floats2bfloat162_rn(x1, y1);
            } else {
                *(float2*)&C[(size_t)ra*256 + col] = make_float2(x0, y0);
                *(float2*)&C[(size_t)rb*256 + col] = make_float2(x1, y1);
            }
        }
    }
}

// ---------------------------------------------------------------------------
// Flash attention, no-max softmax (p = 2^(s-16), exact after normalization),
// register-resident P, 4-deep cp.async ring with ONE barrier per tile.
// BQ=128, BK=64, 512 threads, 16 warps: wm = wid&7 (16 rows), wn = wid>>3
// (PV col half). Row sums accumulate thread-locally; single quad-reduce at end.
// ---------------------------------------------------------------------------
#define BQ 128
#define BK 64
#define NT (NTOK/BK)
#define QK_STR 40    // bf16 elems (80B rows)
#define V_STRB 264   // bf16 elems (528B rows)

#define SM_QS  0
#define SM_KB(i) (10240 + (i)*5120)           // 4 x 64x40 bf16
#define SM_VB(i) (30720 + (i)*33792)          // 4 x 64x264 bf16
#define ATT_SMEM_BYTES (30720 + 4*33792)      // 165888

__global__ __launch_bounds__(512, 1) void attn_kernel()
{
    extern __shared__ char sm[];
    const unsigned smb = smem_u32(sm);

    const int tid  = threadIdx.x;
    const int wid  = tid >> 5;
    const int lane = tid & 31;
    const int gid  = lane >> 2;
    const int tig  = lane & 3;
    const int wm   = wid & 7;      // rows wm*16 .. +16
    const int wn   = wid >> 3;     // PV cols wn*128 .. +128
    const int arow = lane & 15;
    const int akof = (lane >> 4) * 8;

    const int b  = blockIdx.y;
    const int q0 = blockIdx.x * BQ;

    const __nv_bfloat16* qg = g_q + (size_t)b * NTOK * DDIM;
    const __nv_bfloat16* kg = g_k + (size_t)b * NTOK * DDIM;
    const __nv_bfloat16* vg = g_v + (size_t)b * NTOK * CDIM;
    __nv_bfloat16*       og = g_att + (size_t)b * NTOK * CDIM;

    // Per-thread load coordinates
    const int kr = tid >> 2, kc = (tid & 3) * 8;       // K: first 256 threads

    // Prologue: Q + tiles 0,1
    {
        int r = tid >> 2, c8 = (tid & 3) * 8;
        cp16(smb + SM_QS + (r*QK_STR + c8)*2, qg + (size_t)q0*DDIM + r*DDIM + c8);
        if (tid < 256)
            cp16(smb + SM_KB(0) + (kr*QK_STR + kc)*2, kg + (size_t)kr*DDIM + kc);
#pragma unroll
        for (int i = 0; i < 4; i++) {
            int idx = tid + i*512;
            int vr = idx >> 5, vc = (idx & 31) * 8;
            cp16(smb + SM_VB(0) + (vr*V_STRB + vc)*2, vg + (size_t)vr*CDIM + vc);
        }
        cp_commit();
        if (tid < 256)
            cp16(smb + SM_KB(1) + (kr*QK_STR + kc)*2,
                 kg + (size_t)(BK + kr)*DDIM + kc);
#pragma unroll
        for (int i = 0; i < 4; i++) {
            int idx = tid + i*512;
            int vr = idx >> 5, vc = (idx & 31) * 8;
            cp16(smb + SM_VB(1) + (vr*V_STRB + vc)*2,
                 vg + (size_t)(BK + vr)*CDIM + vc);
        }
        cp_commit();
    }

    float4 acc[16];
#pragma unroll
    for (int j = 0; j < 16; j++) acc[j] = make_float4(0.f,0.f,0.f,0.f);
    float rl0 = 0.f, rl1 = 0.f;

    const unsigned qa = smb + SM_QS + ((wm*16 + arow)*QK_STR + akof)*2;

    for (int kt = 0; kt < NT; kt++) {
        // Issue tile kt+2 into ring slot (kt+2)&3 (safe: that slot's last
        // reader was tile kt-2, finished 2 barriers ago)
        if (kt + 2 < NT) {
            const int nk0 = (kt + 2) * BK;
            const unsigned kb2 = smb + SM_KB((kt + 2) & 3);
            const unsigned vb2 = smb + SM_VB((kt + 2) & 3);
            if (tid < 256)
                cp16(kb2 + (kr*QK_STR + kc)*2, kg + (size_t)(nk0 + kr)*DDIM + kc);
#pragma unroll
            for (int i = 0; i < 4; i++) {
                int idx = tid + i*512;
                int vr = idx >> 5, vc = (idx & 31) * 8;
                cp16(vb2 + (vr*V_STRB + vc)*2, vg + (size_t)(nk0 + vr)*CDIM + vc);
            }
            cp_commit();
            asm volatile("cp.async.wait_group 2;" ::: "memory");
        } else if (kt + 2 == NT) {
            asm volatile("cp.async.wait_group 1;" ::: "memory");
        } else {
            asm volatile("cp.async.wait_group 0;" ::: "memory");
        }
        __syncthreads();   // tile kt visible to all warps

        const unsigned kbase = smb + SM_KB(kt & 3);
        const unsigned vbase = smb + SM_VB(kt & 3);

        // ---- Scores: S[wm*16..+16][0..64] = Q @ K^T (full strip per warp)
        float4 sacc[8];
#pragma unroll
        for (int i = 0; i < 8; i++) sacc[i] = make_float4(0.f,0.f,0.f,0.f);
        const unsigned kb = kbase + (arow*QK_STR + akof)*2;
#pragma unroll
        for (int ks = 0; ks < 2; ks++) {
            unsigned a0,a1,a2,a3;
            ldm_x4(qa + ks*32, a0,a1,a2,a3);
#pragma unroll
            for (int g = 0; g < 4; g++) {
                unsigned r0,r1,r2,r3;
                ldm_x4(kb + (g*16*QK_STR)*2 + ks*32, r0,r1,r2,r3);
                mma_bf16(sacc[g*2],   a0,a1,a2,a3, r0, r2);
                mma_bf16(sacc[g*2+1], a0,a1,a2,a3, r1, r3);
            }
        }

        // ---- No-max softmax: p = 2^(s - 16); accumulate row sums locally
#pragma unroll
        for (int t = 0; t < 8; t++) {
            sacc[t].x = fast_ex2(sacc[t].x - 16.0f);
            sacc[t].y = fast_ex2(sacc[t].y - 16.0f);
            sacc[t].z = fast_ex2(sacc[t].z - 16.0f);
            sacc[t].w = fast_ex2(sacc[t].w - 16.0f);
            rl0 += sacc[t].x + sacc[t].y;
            rl1 += sacc[t].z + sacc[t].w;
        }

        // Pack P C-fragments directly into bf16 A-fragments (k-blocks of 16)
        unsigned af[4][4];
#pragma unroll
        for (int kk = 0; kk < 4; kk++) {
            af[kk][0] = pack_bf16(sacc[2*kk].x,   sacc[2*kk].y);
            af[kk][1] = pack_bf16(sacc[2*kk].z,   sacc[2*kk].w);
            af[kk][2] = pack_bf16(sacc[2*kk+1].x, sacc[2*kk+1].y);
            af[kk][3] = pack_bf16(sacc[2*kk+1].z, sacc[2*kk+1].w);
        }

        // ---- PV: O[wm*16..+16][wn*128..+128] += P @ V
        const unsigned vb = vbase + (arow*V_STRB + akof)*2;
#pragma unroll
        for (int ks = 0; ks < 4; ks++) {
#pragma unroll
            for (int nt = 0; nt < 8; nt++) {
                unsigned b0,b1,b2,b3;
                ldm_x4_trans(vb + (ks*16*V_STRB + wn*128 + nt*16)*2, b0,b1,b2,b3);
                mma_bf16(acc[nt*2],   af[ks][0],af[ks][1],af[ks][2],af[ks][3], b0,b1);
                mma_bf16(acc[nt*2+1], af[ks][0],af[ks][1],af[ks][2],af[ks][3], b2,b3);
            }
        }
    }

    // ---- Epilogue: one quad-reduce of row sums, normalize, write bf16 ----
    {
        rl0 += __shfl_xor_sync(0xffffffffu, rl0, 1);
        rl0 += __shfl_xor_sync(0xffffffffu, rl0, 2);
        rl1 += __shfl_xor_sync(0xffffffffu, rl1, 1);
        rl1 += __shfl_xor_sync(0xffffffffu, rl1, 2);
        const float inv0 = 1.0f / rl0;
        const float inv1 = 1.0f / rl1;
        __nv_bfloat16* o0 = og + (size_t)(q0 + wm*16 + gid)*CDIM;
        __nv_bfloat16* o1 = o0 + 8*CDIM;
#pragma unroll
        for (int j = 0; j < 16; j++) {
            int c = wn*128 + j*8 + 2*tig;
            *(__nv_bfloat162*)&o0[c] =
                __floats2bfloat162_rn(acc[j].x*inv0, acc[j].y*inv0);
            *(__nv_bfloat162*)&o1[c] =
                __floats2bfloat162_rn(acc[j].z*inv1, acc[j].w*inv1);
        }
    }
}

// ---------------------------------------------------------------------------
// Launch
// ---------------------------------------------------------------------------
extern "C" void kernel_launch(void* const* d_in, const int* in_sizes, int n_in,
                              void* d_out, int out_size)
{
    const float* x  = (const float*)d_in[0];
    const float* wq = (const float*)d_in[1];
    const float* bq = (const float*)d_in[2];
    const float* wk = (const float*)d_in[3];
    const float* bk = (const float*)d_in[4];
    const float* wv = (const float*)d_in[5];
    const float* bv = (const float*)d_in[6];
    const float* wo = (const float*)d_in[7];
    const float* bo = (const float*)d_in[8];
    float* out = (float*)d_out;

    __nv_bfloat16 *q, *k, *v, *att;
    cudaGetSymbolAddress((void**)&q,   g_q);
    cudaGetSymbolAddress((void**)&k,   g_k);
    cudaGetSymbolAddress((void**)&v,   g_v);
    cudaGetSymbolAddress((void**)&att, g_att);

    cudaFuncSetAttribute(attn_kernel,
                         cudaFuncAttributeMaxDynamicSharedMemorySize,
                         ATT_SMEM_BYTES);
    cudaFuncSetAttribute(proj_n256<float, false, __nv_bfloat16>,
                         cudaFuncAttributeMaxDynamicSharedMemorySize, PROJ_SMEM);
    cudaFuncSetAttribute(proj_n256<__nv_bfloat16, true, float>,
                         cudaFuncAttributeMaxDynamicSharedMemorySize, PROJ_SMEM);

    // (1/sqrt(32)) * log2(e): softmax via ex2 with 2^(s-16)
    const float qscale = 0.17677669529663687f * 1.4426950408889634f;

    proj_qk<<<dim3(MTOT/128, 2), 256>>>(x, wq, bq, wk, bk, qscale, q, k);
    proj_n256<float, false, __nv_bfloat16>
        <<<MTOT/128, 256, PROJ_SMEM>>>(x, wv, bv, nullptr, v);

    attn_kernel<<<dim3(NTOK/BQ, BATCH), 512, ATT_SMEM_BYTES>>>();

    proj_n256<__nv_bfloat16, true, float>
        <<<MTOT/128, 256, PROJ_SMEM>>>(att, wo, bo, x, out);
}

// round 15
// speedup vs baseline: 7.2438x; 1.0254x over previous
#include <cuda_runtime.h>
#include <cuda_bf16.h>

// Problem constants
#define BATCH 4
#define NTOK  4096
#define CDIM  256
#define DDIM  32
#define MTOT  (BATCH*NTOK)

// Scratch (allocation-free rule: device globals)
__device__ __nv_bfloat16 g_xb[MTOT*CDIM];
__device__ __nv_bfloat16 g_wqb[CDIM*DDIM];
__device__ __nv_bfloat16 g_wkb[CDIM*DDIM];
__device__ __nv_bfloat16 g_wvb[CDIM*CDIM];
__device__ __nv_bfloat16 g_wob[CDIM*CDIM];
__device__ __nv_bfloat16 g_q[MTOT*DDIM];
__device__ __nv_bfloat16 g_k[MTOT*DDIM];
__device__ __nv_bfloat16 g_v[MTOT*CDIM];
__device__ __nv_bfloat16 g_att[MTOT*CDIM];

// ---------------------------------------------------------------------------
// PTX helpers
// ---------------------------------------------------------------------------
__device__ __forceinline__ unsigned smem_u32(const void* p) {
    return (unsigned)__cvta_generic_to_shared(p);
}
__device__ __forceinline__ void ldm_x4(unsigned addr,
    unsigned &r0, unsigned &r1, unsigned &r2, unsigned &r3) {
    asm volatile("ldmatrix.sync.aligned.m8n8.x4.shared.b16 {%0,%1,%2,%3}, [%4];"
        : "=r"(r0), "=r"(r1), "=r"(r2), "=r"(r3) : "r"(addr));
}
__device__ __forceinline__ void ldm_x4_trans(unsigned addr,
    unsigned &r0, unsigned &r1, unsigned &r2, unsigned &r3) {
    asm volatile("ldmatrix.sync.aligned.m8n8.x4.trans.shared.b16 {%0,%1,%2,%3}, [%4];"
        : "=r"(r0), "=r"(r1), "=r"(r2), "=r"(r3) : "r"(addr));
}
__device__ __forceinline__ void mma_bf16(float4& c,
    unsigned a0, unsigned a1, unsigned a2, unsigned a3,
    unsigned b0, unsigned b1)
{
    asm volatile(
        "mma.sync.aligned.m16n8k16.row.col.f32.bf16.bf16.f32 "
        "{%0,%1,%2,%3}, {%4,%5,%6,%7}, {%8,%9}, {%0,%1,%2,%3};"
        : "+f"(c.x), "+f"(c.y), "+f"(c.z), "+f"(c.w)
        : "r"(a0), "r"(a1), "r"(a2), "r"(a3), "r"(b0), "r"(b1));
}
__device__ __forceinline__ unsigned pack_bf16(float a, float b) {
    __nv_bfloat162 h = __floats2bfloat162_rn(a, b);
    return *(unsigned*)&h;
}
__device__ __forceinline__ float fast_ex2(float x) {
    float y;
    asm("ex2.approx.ftz.f32 %0, %1;" : "=f"(y) : "f"(x));
    return y;
}
__device__ __forceinline__ void cp16(unsigned dst, const void* src) {
    asm volatile("cp.async.cg.shared.global [%0], [%1], 16;"
        :: "r"(dst), "l"(src));
}
__device__ __forceinline__ void cp_commit() {
    asm volatile("cp.async.commit_group;");
}

// ---------------------------------------------------------------------------
// Convert x and all weights fp32 -> bf16 in one launch.
// blocks: [0,4096) x | [4096,4160) wv | [4160,4224) wo | [4224,4232) wq |
//         [4232,4240) wk
// ---------------------------------------------------------------------------
__global__ __launch_bounds__(256) void cvt_all(
    const float4* __restrict__ x,  const float4* __restrict__ wv,
    const float4* __restrict__ wo, const float4* __restrict__ wq,
    const float4* __restrict__ wk,
    uint2* __restrict__ xb,  uint2* __restrict__ wvb,
    uint2* __restrict__ wob, uint2* __restrict__ wqb,
    uint2* __restrict__ wkb)
{
    const int bid = blockIdx.x;
    const float4* src; uint2* dst; int idx;
    if (bid < 4096)      { src = x;  dst = xb;  idx = bid*256 + threadIdx.x; }
    else if (bid < 4160) { src = wv; dst = wvb; idx = (bid-4096)*256 + threadIdx.x; }
    else if (bid < 4224) { src = wo; dst = wob; idx = (bid-4160)*256 + threadIdx.x; }
    else if (bid < 4232) { src = wq; dst = wqb; idx = (bid-4224)*256 + threadIdx.x; }
    else                 { src = wk; dst = wkb; idx = (bid-4232)*256 + threadIdx.x; }
    float4 v = src[idx];
    uint2 o; o.x = pack_bf16(v.x, v.y); o.y = pack_bf16(v.z, v.w);
    dst[idx] = o;
}

// ---------------------------------------------------------------------------
// Q/K projection (bf16 in): C[M][32] = bf16((xb @ W + b) * scale)
// grid (M/128, 2). cp.async double-buffered over 4 k-steps.
// ---------------------------------------------------------------------------
#define PA_STR 72
#define PWQ_STR 40

__global__ __launch_bounds__(256) void proj_qk(
    const __nv_bfloat16* __restrict__ Xb,
    const __nv_bfloat16* __restrict__ wqb, const float* __restrict__ bq,
    const __nv_bfloat16* __restrict__ wkb, const float* __restrict__ bk,
    float qscale,
    __nv_bfloat16* __restrict__ Q, __nv_bfloat16* __restrict__ K)
{
    __shared__ __nv_bfloat16 As[2][128*PA_STR];
    __shared__ __nv_bfloat16 Ws[2][64*PWQ_STR];

    const __nv_bfloat16* W = (blockIdx.y == 0) ? wqb : wkb;
    const float* bias      = (blockIdx.y == 0) ? bq  : bk;
    __nv_bfloat16* C       = (blockIdx.y == 0) ? Q   : K;
    const float scale      = (blockIdx.y == 0) ? qscale : 1.0f;

    const int tid = threadIdx.x;
    const int wid = tid >> 5, lane = tid & 31;
    const int arow = lane & 15, akof = (lane >> 4) * 8;
    const int gid = lane >> 2, tig = lane & 3;
    const int m0 = blockIdx.x * 128;

    const unsigned smA = smem_u32(As);
    const unsigned smW = smem_u32(Ws);

    auto issue = [&](int st, int k0) {
#pragma unroll
        for (int i = 0; i < 4; i++) {               // A: 1024 x 16B
            int idx = tid + i*256;
            int r = idx >> 3, c8 = idx & 7;
            cp16(smA + st*(128*PA_STR*2) + r*(PA_STR*2) + c8*16,
                 Xb + (size_t)(m0 + r)*256 + k0 + c8*8);
        }
        {                                           // W: 256 x 16B
            int r = tid >> 2, c = tid & 3;
            cp16(smW + st*(64*PWQ_STR*2) + r*(PWQ_STR*2) + c*16,
                 W + (size_t)(k0 + r)*32 + c*8);
        }
        cp_commit();
    };

    issue(0, 0);
    issue(1, 64);

    float4 acc[4];
#pragma unroll
    for (int i = 0; i < 4; i++) acc[i] = make_float4(0.f,0.f,0.f,0.f);

    for (int k = 0; k < 4; k++) {
        if (k == 3) asm volatile("cp.async.wait_group 0;" ::: "memory");
        else        asm volatile("cp.async.wait_group 1;" ::: "memory");
        __syncthreads();

        const int st = k & 1;
        const unsigned aa = smA + st*(128*PA_STR*2) + ((wid*16 + arow)*PA_STR + akof)*2;
        const unsigned wb = smW + st*(64*PWQ_STR*2) + (arow*PWQ_STR + akof)*2;
#pragma unroll
        for (int ks = 0; ks < 4; ks++) {
            unsigned a0,a1,a2,a3;
            ldm_x4(aa + ks*32, a0,a1,a2,a3);
#pragma unroll
            for (int nt2 = 0; nt2 < 2; nt2++) {
                unsigned b0,b1,b2,b3;
                ldm_x4_trans(wb + (ks*16*PWQ_STR + nt2*16)*2, b0,b1,b2,b3);
                mma_bf16(acc[nt2*2],   a0,a1,a2,a3, b0,b1);
                mma_bf16(acc[nt2*2+1], a0,a1,a2,a3, b2,b3);
            }
        }
        if (k + 2 < 4) {
            __syncthreads();
            issue(st, (k + 2)*64);
        }
    }

    const int r0 = m0 + wid*16 + gid;
#pragma unroll
    for (int j = 0; j < 4; j++) {
        int col = j*8 + 2*tig;
        float b0 = bias[col], b1 = bias[col+1];
        *(__nv_bfloat162*)&C[(size_t)r0*32 + col] =
            __floats2bfloat162_rn((acc[j].x + b0)*scale, (acc[j].y + b1)*scale);
        *(__nv_bfloat162*)&C[(size_t)(r0+8)*32 + col] =
            __floats2bfloat162_rn((acc[j].z + b0)*scale, (acc[j].w + b1)*scale);
    }
}

// ---------------------------------------------------------------------------
// N=256 projection (bf16 A and W): C = A @ W + b (+fp32 resid).
// cp.async double-buffered over 4 k-steps. OUT = bf16 (v) or float (out).
// ---------------------------------------------------------------------------
#define PW_STR 264
#define PROJ_SMEM (2*128*PA_STR*2 + 2*64*PW_STR*2)   // 104448

template<bool RESID, typename OUT>
__global__ __launch_bounds__(256) void proj_n256p(
    const __nv_bfloat16* __restrict__ A, const __nv_bfloat16* __restrict__ W,
    const float* __restrict__ bias, const float* __restrict__ resid,
    OUT* __restrict__ C)
{
    extern __shared__ char psm[];
    const unsigned smA = smem_u32(psm);
    const unsigned smW = smA + 2*128*PA_STR*2;

    const int tid = threadIdx.x;
    const int wid = tid >> 5, lane = tid & 31;
    const int wm = wid & 3, wn = wid >> 2;
    const int arow = lane & 15, akof = (lane >> 4) * 8;
    const int gid = lane >> 2, tig = lane & 3;
    const int m0 = blockIdx.x * 128;

    auto issue = [&](int st, int k0) {
#pragma unroll
        for (int i = 0; i < 4; i++) {               // A: 1024 x 16B
            int idx = tid + i*256;
            int r = idx >> 3, c8 = idx & 7;
            cp16(smA + st*(128*PA_STR*2) + r*(PA_STR*2) + c8*16,
                 A + (size_t)(m0 + r)*256 + k0 + c8*8);
        }
#pragma unroll
        for (int i = 0; i < 8; i++) {               // W: 2048 x 16B
            int idx = tid + i*256;
            int r = idx >> 5, c = idx & 31;
            cp16(smW + st*(64*PW_STR*2) + r*(PW_STR*2) + c*16,
                 W + (size_t)(k0 + r)*256 + c*8);
        }
        cp_commit();
    };

    issue(0, 0);
    issue(1, 64);

    float4 acc[2][16];
#pragma unroll
    for (int i = 0; i < 2; i++)
#pragma unroll
        for (int j = 0; j < 16; j++) acc[i][j] = make_float4(0.f,0.f,0.f,0.f);

    for (int k = 0; k < 4; k++) {
        if (k == 3) asm volatile("cp.async.wait_group 0;" ::: "memory");
        else        asm volatile("cp.async.wait_group 1;" ::: "memory");
        __syncthreads();

        const int st = k & 1;
        const unsigned aa0 = smA + st*(128*PA_STR*2) + ((wm*32 + arow)*PA_STR + akof)*2;
        const unsigned aa1 = aa0 + 16*PA_STR*2;
        const unsigned wb  = smW + st*(64*PW_STR*2) + (arow*PW_STR + akof)*2;
#pragma unroll
        for (int ks = 0; ks < 4; ks++) {
            unsigned a00,a01,a02,a03, a10,a11,a12,a13;
            ldm_x4(aa0 + ks*32, a00,a01,a02,a03);
            ldm_x4(aa1 + ks*32, a10,a11,a12,a13);
#pragma unroll
            for (int nt = 0; nt < 8; nt++) {
                unsigned b0,b1,b2,b3;
                ldm_x4_trans(wb + (ks*16*PW_STR + wn*128 + nt*16)*2, b0,b1,b2,b3);
                mma_bf16(acc[0][nt*2],   a00,a01,a02,a03, b0,b1);
                mma_bf16(acc[0][nt*2+1], a00,a01,a02,a03, b2,b3);
                mma_bf16(acc[1][nt*2],   a10,a11,a12,a13, b0,b1);
                mma_bf16(acc[1][nt*2+1], a10,a11,a12,a13, b2,b3);
            }
        }
        if (k + 2 < 4) {
            __syncthreads();
            issue(st, (k + 2)*64);
        }
    }

#pragma unroll
    for (int ms = 0; ms < 2; ms++) {
        int ra = m0 + wm*32 + ms*16 + gid;
        int rb = ra + 8;
#pragma unroll
        for (int j = 0; j < 16; j++) {
            int col = wn*128 + j*8 + 2*tig;
            float b0 = bias[col], b1 = bias[col+1];
            float x0 = acc[ms][j].x + b0, y0 = acc[ms][j].y + b1;
            float x1 = acc[ms][j].z + b0, y1 = acc[ms][j].w + b1;
            if (RESID) {
                float2 ra2 = *(const float2*)&resid[(size_t)ra*256 + col];
                float2 rb2 = *(const float2*)&resid[(size_t)rb*256 + col];
                x0 += ra2.x; y0 += ra2.y; x1 += rb2.x; y1 += rb2.y;
            }
            if constexpr (sizeof(OUT) == 2) {
                *(__nv_bfloat162*)&C[(size_t)ra*256 + col] = __floats2bfloat162_rn(x0, y0);
                *(__nv_bfloat162*)&C[(size_t)rb*256 + col] = __floats2bfloat162_rn(x1, y1);
            } else {
                *(float2*)&C[(size_t)ra*256 + col] = make_float2(x0, y0);
                *(float2*)&C[(size_t)rb*256 + col] = make_float2(x1, y1);
            }
        }
    }
}

// ---------------------------------------------------------------------------
// Flash attention, no-max softmax (p = 2^(s-16), exact after normalization),
// register-resident P, 4-deep cp.async ring with ONE barrier per tile.
// (unchanged from round 11)
// ---------------------------------------------------------------------------
#define BQ 128
#define BK 64
#define NT (NTOK/BK)
#define QK_STR 40
#define V_STRB 264

#define SM_QS  0
#define SM_KB(i) (10240 + (i)*5120)
#define SM_VB(i) (30720 + (i)*33792)
#define ATT_SMEM_BYTES (30720 + 4*33792)

__global__ __launch_bounds__(512, 1) void attn_kernel()
{
    extern __shared__ char sm[];
    const unsigned smb = smem_u32(sm);

    const int tid  = threadIdx.x;
    const int wid  = tid >> 5;
    const int lane = tid & 31;
    const int gid  = lane >> 2;
    const int tig  = lane & 3;
    const int wm   = wid & 7;
    const int wn   = wid >> 3;
    const int arow = lane & 15;
    const int akof = (lane >> 4) * 8;

    const int b  = blockIdx.y;
    const int q0 = blockIdx.x * BQ;

    const __nv_bfloat16* qg = g_q + (size_t)b * NTOK * DDIM;
    const __nv_bfloat16* kg = g_k + (size_t)b * NTOK * DDIM;
    const __nv_bfloat16* vg = g_v + (size_t)b * NTOK * CDIM;
    __nv_bfloat16*       og = g_att + (size_t)b * NTOK * CDIM;

    const int kr = tid >> 2, kc = (tid & 3) * 8;

    {
        int r = tid >> 2, c8 = (tid & 3) * 8;
        cp16(smb + SM_QS + (r*QK_STR + c8)*2, qg + (size_t)q0*DDIM + r*DDIM + c8);
        if (tid < 256)
            cp16(smb + SM_KB(0) + (kr*QK_STR + kc)*2, kg + (size_t)kr*DDIM + kc);
#pragma unroll
        for (int i = 0; i < 4; i++) {
            int idx = tid + i*512;
            int vr = idx >> 5, vc = (idx & 31) * 8;
            cp16(smb + SM_VB(0) + (vr*V_STRB + vc)*2, vg + (size_t)vr*CDIM + vc);
        }
        cp_commit();
        if (tid < 256)
            cp16(smb + SM_KB(1) + (kr*QK_STR + kc)*2,
                 kg + (size_t)(BK + kr)*DDIM + kc);
#pragma unroll
        for (int i = 0; i < 4; i++) {
            int idx = tid + i*512;
            int vr = idx >> 5, vc = (idx & 31) * 8;
            cp16(smb + SM_VB(1) + (vr*V_STRB + vc)*2,
                 vg + (size_t)(BK + vr)*CDIM + vc);
        }
        cp_commit();
    }

    float4 acc[16];
#pragma unroll
    for (int j = 0; j < 16; j++) acc[j] = make_float4(0.f,0.f,0.f,0.f);
    float rl0 = 0.f, rl1 = 0.f;

    const unsigned qa = smb + SM_QS + ((wm*16 + arow)*QK_STR + akof)*2;

    for (int kt = 0; kt < NT; kt++) {
        if (kt + 2 < NT) {
            const int nk0 = (kt + 2) * BK;
            const unsigned kb2 = smb + SM_KB((kt + 2) & 3);
            const unsigned vb2 = smb + SM_VB((kt + 2) & 3);
            if (tid < 256)
                cp16(kb2 + (kr*QK_STR + kc)*2, kg + (size_t)(nk0 + kr)*DDIM + kc);
#pragma unroll
            for (int i = 0; i < 4; i++) {
                int idx = tid + i*512;
                int vr = idx >> 5, vc = (idx & 31) * 8;
                cp16(vb2 + (vr*V_STRB + vc)*2, vg + (size_t)(nk0 + vr)*CDIM + vc);
            }
            cp_commit();
            asm volatile("cp.async.wait_group 2;" ::: "memory");
        } else if (kt + 2 == NT) {
            asm volatile("cp.async.wait_group 1;" ::: "memory");
        } else {
            asm volatile("cp.async.wait_group 0;" ::: "memory");
        }
        __syncthreads();

        const unsigned kbase = smb + SM_KB(kt & 3);
        const unsigned vbase = smb + SM_VB(kt & 3);

        float4 sacc[8];
#pragma unroll
        for (int i = 0; i < 8; i++) sacc[i] = make_float4(0.f,0.f,0.f,0.f);
        const unsigned kb = kbase + (arow*QK_STR + akof)*2;
#pragma unroll
        for (int ks = 0; ks < 2; ks++) {
            unsigned a0,a1,a2,a3;
            ldm_x4(qa + ks*32, a0,a1,a2,a3);
#pragma unroll
            for (int g = 0; g < 4; g++) {
                unsigned r0,r1,r2,r3;
                ldm_x4(kb + (g*16*QK_STR)*2 + ks*32, r0,r1,r2,r3);
                mma_bf16(sacc[g*2],   a0,a1,a2,a3, r0, r2);
                mma_bf16(sacc[g*2+1], a0,a1,a2,a3, r1, r3);
            }
        }

#pragma unroll
        for (int t = 0; t < 8; t++) {
            sacc[t].x = fast_ex2(sacc[t].x - 16.0f);
            sacc[t].y = fast_ex2(sacc[t].y - 16.0f);
            sacc[t].z = fast_ex2(sacc[t].z - 16.0f);
            sacc[t].w = fast_ex2(sacc[t].w - 16.0f);
            rl0 += sacc[t].x + sacc[t].y;
            rl1 += sacc[t].z + sacc[t].w;
        }

        unsigned af[4][4];
#pragma unroll
        for (int kk = 0; kk < 4; kk++) {
            af[kk][0] = pack_bf16(sacc[2*kk].x,   sacc[2*kk].y);
            af[kk][1] = pack_bf16(sacc[2*kk].z,   sacc[2*kk].w);
            af[kk][2] = pack_bf16(sacc[2*kk+1].x, sacc[2*kk+1].y);
            af[kk][3] = pack_bf16(sacc[2*kk+1].z, sacc[2*kk+1].w);
        }

        const unsigned vb = vbase + (arow*V_STRB + akof)*2;
#pragma unroll
        for (int ks = 0; ks < 4; ks++) {
#pragma unroll
            for (int nt = 0; nt < 8; nt++) {
                unsigned b0,b1,b2,b3;
                ldm_x4_trans(vb + (ks*16*V_STRB + wn*128 + nt*16)*2, b0,b1,b2,b3);
                mma_bf16(acc[nt*2],   af[ks][0],af[ks][1],af[ks][2],af[ks][3], b0,b1);
                mma_bf16(acc[nt*2+1], af[ks][0],af[ks][1],af[ks][2],af[ks][3], b2,b3);
            }
        }
    }

    {
        rl0 += __shfl_xor_sync(0xffffffffu, rl0, 1);
        rl0 += __shfl_xor_sync(0xffffffffu, rl0, 2);
        rl1 += __shfl_xor_sync(0xffffffffu, rl1, 1);
        rl1 += __shfl_xor_sync(0xffffffffu, rl1, 2);
        const float inv0 = 1.0f / rl0;
        const float inv1 = 1.0f / rl1;
        __nv_bfloat16* o0 = og + (size_t)(q0 + wm*16 + gid)*CDIM;
        __nv_bfloat16* o1 = o0 + 8*CDIM;
#pragma unroll
        for (int j = 0; j < 16; j++) {
            int c = wn*128 + j*8 + 2*tig;
            *(__nv_bfloat162*)&o0[c] =
                __floats2bfloat162_rn(acc[j].x*inv0, acc[j].y*inv0);
            *(__nv_bfloat162*)&o1[c] =
                __floats2bfloat162_rn(acc[j].z*inv1, acc[j].w*inv1);
        }
    }
}

// ---------------------------------------------------------------------------
// Launch
// ---------------------------------------------------------------------------
extern "C" void kernel_launch(void* const* d_in, const int* in_sizes, int n_in,
                              void* d_out, int out_size)
{
    const float* x  = (const float*)d_in[0];
    const float* wq = (const float*)d_in[1];
    const float* bq = (const float*)d_in[2];
    const float* wk = (const float*)d_in[3];
    const float* bk = (const float*)d_in[4];
    const float* wv = (const float*)d_in[5];
    const float* bv = (const float*)d_in[6];
    const float* wo = (const float*)d_in[7];
    const float* bo = (const float*)d_in[8];
    float* out = (float*)d_out;

    __nv_bfloat16 *xb, *wqb, *wkb, *wvb, *wob, *q, *k, *v, *att;
    cudaGetSymbolAddress((void**)&xb,  g_xb);
    cudaGetSymbolAddress((void**)&wqb, g_wqb);
    cudaGetSymbolAddress((void**)&wkb, g_wkb);
    cudaGetSymbolAddress((void**)&wvb, g_wvb);
    cudaGetSymbolAddress((void**)&wob, g_wob);
    cudaGetSymbolAddress((void**)&q,   g_q);
    cudaGetSymbolAddress((void**)&k,   g_k);
    cudaGetSymbolAddress((void**)&v,   g_v);
    cudaGetSymbolAddress((void**)&att, g_att);

    cudaFuncSetAttribute(attn_kernel,
                         cudaFuncAttributeMaxDynamicSharedMemorySize,
                         ATT_SMEM_BYTES);
    cudaFuncSetAttribute(proj_n256p<false, __nv_bfloat16>,
                         cudaFuncAttributeMaxDynamicSharedMemorySize, PROJ_SMEM);
    cudaFuncSetAttribute(proj_n256p<true, float>,
                         cudaFuncAttributeMaxDynamicSharedMemorySize, PROJ_SMEM);

    // (1/sqrt(32)) * log2(e): softmax via ex2 with 2^(s-16)
    const float qscale = 0.17677669529663687f * 1.4426950408889634f;

    cvt_all<<<4240, 256>>>((const float4*)x, (const float4*)wv,
                           (const float4*)wo, (const float4*)wq,
                           (const float4*)wk,
                           (uint2*)xb, (uint2*)wvb, (uint2*)wob,
                           (uint2*)wqb, (uint2*)wkb);

    proj_qk<<<dim3(MTOT/128, 2), 256>>>(xb, wqb, bq, wkb, bk, qscale, q, k);
    proj_n256p<false, __nv_bfloat16>
        <<<MTOT/128, 256, PROJ_SMEM>>>(xb, wvb, bv, nullptr, v);

    attn_kernel<<<dim3(NTOK/BQ, BATCH), 512, ATT_SMEM_BYTES>>>();

    proj_n256p<true, float>
        <<<MTOT/128, 256, PROJ_SMEM>>>(att, wob, bo, x, out);
}